// round 10
// baseline (speedup 1.0000x reference)
#include <cuda_runtime.h>
#include <cuda_fp16.h>
#include <cstdint>

// Problem constants
#define Bc  4
#define Tc  2048
#define Cc  1024
#define NHc 16
#define HDc 64

// ---------------------------------------------------------------------------
// Scratch (no cudaMalloc allowed)
// ---------------------------------------------------------------------------
__device__ __half g_qh[Bc * NHc * Tc * HDc];   // [B*NH, T, HD]
__device__ __half g_kh[Bc * NHc * Tc * HDc];
__device__ __half g_vh[Bc * NHc * Tc * HDc];
__device__ __half g_yh[Bc * Tc * Cc];          // attention out [B,T,C]
__device__ __half g_wa_th[3 * Cc * Cc];        // W_attn^T [3C, C]
__device__ __half g_wp_th[Cc * Cc];            // W_proj^T [C, C]

__device__ __forceinline__ uint32_t smem_u32(const void* p) {
    uint32_t a;
    asm("{ .reg .u64 t; cvta.to.shared.u64 t, %1; cvt.u32.u64 %0, t; }" : "=r"(a) : "l"(p));
    return a;
}
__device__ __forceinline__ void cp16(uint32_t dst, const void* src) {
    asm volatile("cp.async.cg.shared.global [%0], [%1], 16;" :: "r"(dst), "l"(src));
}
__device__ __forceinline__ void cp_commit() {
    asm volatile("cp.async.commit_group;" ::: "memory");
}
template <int N>
__device__ __forceinline__ void cp_wait() {
    asm volatile("cp.async.wait_group %0;" :: "n"(N) : "memory");
}
__device__ __forceinline__ uint32_t h2u(__half2 h) { return *reinterpret_cast<uint32_t*>(&h); }
__device__ __forceinline__ uint32_t packh(float a, float b) {
    return h2u(__float22half2_rn(make_float2(a, b)));
}

__device__ __forceinline__ void mma_f16(float& d0, float& d1, float& d2, float& d3,
                                        uint32_t a0, uint32_t a1, uint32_t a2, uint32_t a3,
                                        uint32_t b0, uint32_t b1)
{
    asm volatile(
        "mma.sync.aligned.m16n8k16.row.col.f32.f16.f16.f32 "
        "{%0,%1,%2,%3}, {%4,%5,%6,%7}, {%8,%9}, {%0,%1,%2,%3};"
        : "+f"(d0), "+f"(d1), "+f"(d2), "+f"(d3)
        : "r"(a0), "r"(a1), "r"(a2), "r"(a3), "r"(b0), "r"(b1));
}
__device__ __forceinline__ void ldm_x4(uint32_t& r0, uint32_t& r1, uint32_t& r2, uint32_t& r3,
                                       uint32_t addr)
{
    asm volatile("ldmatrix.sync.aligned.m8n8.x4.shared.b16 {%0,%1,%2,%3}, [%4];"
                 : "=r"(r0), "=r"(r1), "=r"(r2), "=r"(r3) : "r"(addr));
}
__device__ __forceinline__ void ldm_x4_t(uint32_t& r0, uint32_t& r1, uint32_t& r2, uint32_t& r3,
                                         uint32_t addr)
{
    asm volatile("ldmatrix.sync.aligned.m8n8.x4.trans.shared.b16 {%0,%1,%2,%3}, [%4];"
                 : "=r"(r0), "=r"(r1), "=r"(r2), "=r"(r3) : "r"(addr));
}

// ---------------------------------------------------------------------------
// fp16 mma GEMM: Out[M,N] = A[M,K]@Bt[N,K]^T + bias.
// Block 128x256, BK=32, 256 threads, 8 warps in 2x4 -> 64x64 warp tiles
// (0.5 LDS.64 per mma, 1.5x less L1 traffic than 64x32).
// CONVA=1: A is fp32, converted in the load path (GEMM1 reads x directly).
// SCATTER=1: half epilogue into g_qh/g_kh/g_vh; else fp32 Out.
// ---------------------------------------------------------------------------
constexpr int BMg = 128, BNg = 256;
constexpr int SMEM_G = (2 * 2 * BMg * 4 + 2 * 2 * BNg * 4) * 8;   // 49152 B

template <int SCATTER, int CONVA>
__global__ __launch_bounds__(256, 1)
void gemm_h(const void* __restrict__ Avp, const __half* __restrict__ Bt,
            const float* __restrict__ bias, float* __restrict__ Out,
            int K, int N)
{
    extern __shared__ uint2 sg[];
    uint2* As2 = sg;                    // [buf][ks][128][4]
    uint2* Bs2 = sg + 2 * 2 * BMg * 4;  // [buf][ks][256][4]

    const int tid  = threadIdx.x;
    const int lane = tid & 31;
    const int wid  = tid >> 5;
    const int g    = lane >> 2;
    const int c    = lane & 3;
    const int warp_m = (wid & 1) * 64;
    const int warp_n = (wid >> 1) * 64;

    const int row  = tid >> 1;          // 0..127
    const int half = tid & 1;

    const __half* Ah = (const __half*)Avp;
    const float*  Af = (const float*)Avp;
    const size_t arow = (size_t)(blockIdx.y * BMg + row);
    const __half* Bp0 = Bt + (size_t)(blockIdx.x * BNg + row) * K + half * 16;
    const __half* Bp1 = Bp0 + (size_t)128 * K;

    uint4 au, av, bu0, bv0, bu1, bv1;

    auto ldg_tile = [&](int k0) {
        if (CONVA) {
            const float* ap = Af + arow * K + half * 16 + k0;
            float4 f0 = *(const float4*)(ap);
            float4 f1 = *(const float4*)(ap + 4);
            float4 f2 = *(const float4*)(ap + 8);
            float4 f3 = *(const float4*)(ap + 12);
            au.x = packh(f0.x, f0.y);  au.y = packh(f0.z, f0.w);
            au.z = packh(f1.x, f1.y);  au.w = packh(f1.z, f1.w);
            av.x = packh(f2.x, f2.y);  av.y = packh(f2.z, f2.w);
            av.z = packh(f3.x, f3.y);  av.w = packh(f3.z, f3.w);
        } else {
            const __half* ap = Ah + arow * K + half * 16 + k0;
            au = *(const uint4*)(ap);
            av = *(const uint4*)(ap + 8);
        }
        bu0 = *(const uint4*)(Bp0 + k0);
        bv0 = *(const uint4*)(Bp0 + k0 + 8);
        bu1 = *(const uint4*)(Bp1 + k0);
        bv1 = *(const uint4*)(Bp1 + k0 + 8);
    };
    auto sts_tile = [&](int buf) {
        uint2* Ad = As2 + ((buf * 2 + half) * BMg + row) * 4;
        Ad[0] = make_uint2(au.x, av.x);
        Ad[1] = make_uint2(au.y, av.y);
        Ad[2] = make_uint2(au.z, av.z);
        Ad[3] = make_uint2(au.w, av.w);
        uint2* Bd0 = Bs2 + ((buf * 2 + half) * BNg + row) * 4;
        Bd0[0] = make_uint2(bu0.x, bv0.x);
        Bd0[1] = make_uint2(bu0.y, bv0.y);
        Bd0[2] = make_uint2(bu0.z, bv0.z);
        Bd0[3] = make_uint2(bu0.w, bv0.w);
        uint2* Bd1 = Bs2 + ((buf * 2 + half) * BNg + row + 128) * 4;
        Bd1[0] = make_uint2(bu1.x, bv1.x);
        Bd1[1] = make_uint2(bu1.y, bv1.y);
        Bd1[2] = make_uint2(bu1.z, bv1.z);
        Bd1[3] = make_uint2(bu1.w, bv1.w);
    };

    float acc[4][8][4];
#pragma unroll
    for (int i = 0; i < 4; i++)
#pragma unroll
        for (int j = 0; j < 8; j++)
#pragma unroll
            for (int r = 0; r < 4; r++) acc[i][j][r] = 0.f;

    const int NT = K / 32;
    ldg_tile(0);
    sts_tile(0);
    __syncthreads();

    for (int kt = 0; kt < NT; kt++) {
        const int buf = kt & 1;
        if (kt + 1 < NT) ldg_tile((kt + 1) * 32);

#pragma unroll
        for (int ks = 0; ks < 2; ks++) {
            uint32_t af[4][4], bf[8][2];
#pragma unroll
            for (int mt = 0; mt < 4; mt++) {
                uint2 lo = As2[((buf * 2 + ks) * BMg + warp_m + mt * 16 + g) * 4 + c];
                uint2 hi = As2[((buf * 2 + ks) * BMg + warp_m + mt * 16 + 8 + g) * 4 + c];
                af[mt][0] = lo.x;  af[mt][1] = hi.x;
                af[mt][2] = lo.y;  af[mt][3] = hi.y;
            }
#pragma unroll
            for (int nt = 0; nt < 8; nt++) {
                uint2 bb = Bs2[((buf * 2 + ks) * BNg + warp_n + nt * 8 + g) * 4 + c];
                bf[nt][0] = bb.x;  bf[nt][1] = bb.y;
            }
#pragma unroll
            for (int mt = 0; mt < 4; mt++)
#pragma unroll
                for (int nt = 0; nt < 8; nt++)
                    mma_f16(acc[mt][nt][0], acc[mt][nt][1], acc[mt][nt][2], acc[mt][nt][3],
                            af[mt][0], af[mt][1], af[mt][2], af[mt][3],
                            bf[nt][0], bf[nt][1]);
        }
        __syncthreads();
        if (kt + 1 < NT) {
            sts_tile(buf ^ 1);
            __syncthreads();
        }
    }

#pragma unroll
    for (int mt = 0; mt < 4; mt++) {
#pragma unroll
        for (int nt = 0; nt < 8; nt++) {
            int n0 = blockIdx.x * BNg + warp_n + nt * 8 + 2 * c;
            float2 bb = *(const float2*)(bias + n0);
            int m0 = blockIdx.y * BMg + warp_m + mt * 16 + g;
#pragma unroll
            for (int rh = 0; rh < 2; rh++) {
                int m = m0 + rh * 8;
                float vx = acc[mt][nt][2 * rh + 0] + bb.x;
                float vy = acc[mt][nt][2 * rh + 1] + bb.y;
                if (SCATTER) {
                    __half2 hv = __float22half2_rn(make_float2(vx, vy));
                    int which = n0 >> 10, c0 = n0 & 1023;
                    int h = c0 >> 6, d = c0 & 63;
                    int b = m >> 11, t = m & 2047;
                    __half* dst = (which == 0) ? g_qh : ((which == 1) ? g_kh : g_vh);
                    *(__half2*)&dst[(((size_t)(b * NHc + h)) * Tc + t) * HDc + d] = hv;
                } else {
                    *(float2*)&Out[(size_t)m * N + n0] = make_float2(vx, vy);
                }
            }
        }
    }
}

// ---------------------------------------------------------------------------
// Prep: transpose + fp32->fp16 for weights
// ---------------------------------------------------------------------------
__global__ void transpose_conv(const float* __restrict__ W, __half* __restrict__ Bt,
                               int K, int N)
{
    __shared__ float t[32][33];
    int n0 = blockIdx.x * 32, k0 = blockIdx.y * 32;
    int tx = threadIdx.x, ty = threadIdx.y;
#pragma unroll
    for (int i = 0; i < 32; i += 8)
        t[ty + i][tx] = W[(size_t)(k0 + ty + i) * N + n0 + tx];
    __syncthreads();
#pragma unroll
    for (int i = 0; i < 32; i += 8)
        Bt[(size_t)(n0 + ty + i) * K + k0 + tx] = __float2half_rn(t[tx][ty + i]);
}

// ---------------------------------------------------------------------------
// FA2 attention, fp16 mma m16n8k16 (unchanged from R9 — passing, ~130us).
// ---------------------------------------------------------------------------
constexpr int QTile = 128;
constexpr int KTile = 64;
constexpr int KVSH  = 72;
constexpr int ATTN_SMEM = 2 * 2 * KTile * KVSH * 2;      // 36864 B

__global__ __launch_bounds__(256)
void attn_h()
{
    extern __shared__ __half smh[];
    __half* KsBase = smh;
    __half* VsBase = smh + 2 * KTile * KVSH;

    const int qt  = (gridDim.x - 1) - blockIdx.x;
    const int bh  = blockIdx.y;
    const int qb  = qt * QTile;
    const int tid = threadIdx.x;
    const int lane = tid & 31;
    const int w   = tid >> 5;
    const int g   = lane >> 2;
    const int c   = lane & 3;

    const __half* gq = g_qh + (size_t)bh * Tc * HDc;
    const __half* gk = g_kh + (size_t)bh * Tc * HDc;
    const __half* gv = g_vh + (size_t)bh * Tc * HDc;

    const int r0 = qb + w * 16 + g;

    const __half2 scl = __float2half2_rn(0.125f);
    const __half2* q0p = (const __half2*)(gq + (size_t)r0 * HDc);
    const __half2* q1p = (const __half2*)(gq + (size_t)(r0 + 8) * HDc);
    uint32_t aq[4][4];
#pragma unroll
    for (int kk = 0; kk < 4; kk++) {
        aq[kk][0] = h2u(__hmul2(q0p[8 * kk + c],     scl));
        aq[kk][1] = h2u(__hmul2(q1p[8 * kk + c],     scl));
        aq[kk][2] = h2u(__hmul2(q0p[8 * kk + c + 4], scl));
        aq[kk][3] = h2u(__hmul2(q1p[8 * kk + c + 4], scl));
    }

    float o[8][4];
#pragma unroll
    for (int nt = 0; nt < 8; nt++)
#pragma unroll
        for (int j = 0; j < 4; j++) o[nt][j] = 0.f;
    float m0 = -1e30f, m1 = -1e30f, l0 = 0.f, l1 = 0.f;

    auto load_kv = [&](int t, int buf) {
        const __half* ksrc = gk + (size_t)t * KTile * HDc;
        const __half* vsrc = gv + (size_t)t * KTile * HDc;
        __half* kd = KsBase + buf * KTile * KVSH;
        __half* vd = VsBase + buf * KTile * KVSH;
#pragma unroll
        for (int i = 0; i < 2; i++) {
            int id = tid + i * 256;
            int row = id >> 3, ch = (id & 7) * 8;
            cp16(smem_u32(kd + row * KVSH + ch), ksrc + row * HDc + ch);
            cp16(smem_u32(vd + row * KVSH + ch), vsrc + row * HDc + ch);
        }
    };

    const int NT = 2 * (qt + 1);
    load_kv(0, 0); cp_commit();

    for (int t = 0; t < NT; t++) {
        const int buf = t & 1;
        if (t + 1 < NT) { load_kv(t + 1, buf ^ 1); cp_commit(); cp_wait<1>(); }
        else            { cp_wait<0>(); }
        __syncthreads();

        const uint32_t ksb = smem_u32(KsBase + buf * KTile * KVSH);
        const uint32_t vsb = smem_u32(VsBase + buf * KTile * KVSH);
        const int kb = t * KTile;

        float s[8][4];
#pragma unroll
        for (int nt = 0; nt < 8; nt++)
#pragma unroll
            for (int j = 0; j < 4; j++) s[nt][j] = 0.f;

#pragma unroll
        for (int nt = 0; nt < 8; nt++) {
            uint32_t k0r, k1r, k2r, k3r;
            uint32_t addr = ksb + (uint32_t)(((nt * 8 + (lane & 7)) * KVSH + (lane >> 3) * 8) * 2);
            ldm_x4(k0r, k1r, k2r, k3r, addr);
            mma_f16(s[nt][0], s[nt][1], s[nt][2], s[nt][3],
                    aq[0][0], aq[0][1], aq[0][2], aq[0][3], k0r, k1r);
            mma_f16(s[nt][0], s[nt][1], s[nt][2], s[nt][3],
                    aq[1][0], aq[1][1], aq[1][2], aq[1][3], k2r, k3r);
            ldm_x4(k0r, k1r, k2r, k3r, addr + 64);
            mma_f16(s[nt][0], s[nt][1], s[nt][2], s[nt][3],
                    aq[2][0], aq[2][1], aq[2][2], aq[2][3], k0r, k1r);
            mma_f16(s[nt][0], s[nt][1], s[nt][2], s[nt][3],
                    aq[3][0], aq[3][1], aq[3][2], aq[3][3], k2r, k3r);
        }

        if (kb + KTile - 1 > qb + w * 16) {
#pragma unroll
            for (int nt = 0; nt < 8; nt++) {
                int key0 = kb + nt * 8 + 2 * c;
                if (key0     > r0)     s[nt][0] = -1e30f;
                if (key0 + 1 > r0)     s[nt][1] = -1e30f;
                if (key0     > r0 + 8) s[nt][2] = -1e30f;
                if (key0 + 1 > r0 + 8) s[nt][3] = -1e30f;
            }
        }

        float rm0 = -1e30f, rm1 = -1e30f;
#pragma unroll
        for (int nt = 0; nt < 8; nt++) {
            rm0 = fmaxf(rm0, fmaxf(s[nt][0], s[nt][1]));
            rm1 = fmaxf(rm1, fmaxf(s[nt][2], s[nt][3]));
        }
        rm0 = fmaxf(rm0, __shfl_xor_sync(0xffffffffu, rm0, 1));
        rm0 = fmaxf(rm0, __shfl_xor_sync(0xffffffffu, rm0, 2));
        rm1 = fmaxf(rm1, __shfl_xor_sync(0xffffffffu, rm1, 1));
        rm1 = fmaxf(rm1, __shfl_xor_sync(0xffffffffu, rm1, 2));

        float mn0 = fmaxf(m0, rm0), mn1 = fmaxf(m1, rm1);
        float corr0 = __expf(m0 - mn0), corr1 = __expf(m1 - mn1);
        m0 = mn0; m1 = mn1;

        float ls0 = 0.f, ls1 = 0.f;
        uint32_t pu0[8], pu1[8];
#pragma unroll
        for (int nt = 0; nt < 8; nt++) {
            float p0 = __expf(s[nt][0] - m0);
            float p1 = __expf(s[nt][1] - m0);
            float p2 = __expf(s[nt][2] - m1);
            float p3 = __expf(s[nt][3] - m1);
            ls0 += p0 + p1;  ls1 += p2 + p3;
            pu0[nt] = packh(p0, p1);
            pu1[nt] = packh(p2, p3);
        }
        ls0 += __shfl_xor_sync(0xffffffffu, ls0, 1);
        ls0 += __shfl_xor_sync(0xffffffffu, ls0, 2);
        ls1 += __shfl_xor_sync(0xffffffffu, ls1, 1);
        ls1 += __shfl_xor_sync(0xffffffffu, ls1, 2);
        l0 = l0 * corr0 + ls0;
        l1 = l1 * corr1 + ls1;
#pragma unroll
        for (int nt = 0; nt < 8; nt++) {
            o[nt][0] *= corr0; o[nt][1] *= corr0;
            o[nt][2] *= corr1; o[nt][3] *= corr1;
        }

#pragma unroll
        for (int kk2 = 0; kk2 < 4; kk2++) {
            uint32_t a0 = pu0[2 * kk2],     a1 = pu1[2 * kk2];
            uint32_t a2 = pu0[2 * kk2 + 1], a3 = pu1[2 * kk2 + 1];
#pragma unroll
            for (int ntp = 0; ntp < 4; ntp++) {
                uint32_t v0, v1, v2, v3;
                uint32_t addr = vsb + (uint32_t)((
                    (kk2 * 16 + ((lane >> 3) & 1) * 8 + (lane & 7)) * KVSH +
                    (2 * ntp + (lane >> 4)) * 8) * 2);
                ldm_x4_t(v0, v1, v2, v3, addr);
                mma_f16(o[2 * ntp][0], o[2 * ntp][1], o[2 * ntp][2], o[2 * ntp][3],
                        a0, a1, a2, a3, v0, v1);
                mma_f16(o[2 * ntp + 1][0], o[2 * ntp + 1][1], o[2 * ntp + 1][2], o[2 * ntp + 1][3],
                        a0, a1, a2, a3, v2, v3);
            }
        }
        __syncthreads();
    }

    float inv0 = 1.f / l0, inv1 = 1.f / l1;
    int b = bh >> 4, h = bh & 15;
    __half* y0 = g_yh + ((size_t)b * Tc + r0) * Cc + h * HDc;
    __half* y1 = y0 + (size_t)8 * Cc;
#pragma unroll
    for (int nt = 0; nt < 8; nt++) {
        *(__half2*)&y0[nt * 8 + 2 * c] =
            __float22half2_rn(make_float2(o[nt][0] * inv0, o[nt][1] * inv0));
        *(__half2*)&y1[nt * 8 + 2 * c] =
            __float22half2_rn(make_float2(o[nt][2] * inv1, o[nt][3] * inv1));
    }
}

// ---------------------------------------------------------------------------
// Launch
// ---------------------------------------------------------------------------
extern "C" void kernel_launch(void* const* d_in, const int* in_sizes, int n_in,
                              void* d_out, int out_size)
{
    const float* x      = (const float*)d_in[0];
    const float* W_attn = (const float*)d_in[1];
    const float* b_attn = (const float*)d_in[2];
    const float* W_proj = (const float*)d_in[3];
    const float* b_proj = (const float*)d_in[4];
    float* out = (float*)d_out;

    __half *yh, *wa_t, *wp_t;
    cudaGetSymbolAddress((void**)&yh,   g_yh);
    cudaGetSymbolAddress((void**)&wa_t, g_wa_th);
    cudaGetSymbolAddress((void**)&wp_t, g_wp_th);

    static bool attr_done = false;
    if (!attr_done) {
        cudaFuncSetAttribute(gemm_h<1, 1>, cudaFuncAttributeMaxDynamicSharedMemorySize, SMEM_G);
        cudaFuncSetAttribute(gemm_h<0, 0>, cudaFuncAttributeMaxDynamicSharedMemorySize, SMEM_G);
        cudaFuncSetAttribute(attn_h, cudaFuncAttributeMaxDynamicSharedMemorySize, ATTN_SMEM);
        attr_done = true;
    }

    // Prep: transpose+convert weights (x conversion folded into GEMM1 loads)
    transpose_conv<<<dim3(3 * Cc / 32, Cc / 32), dim3(32, 8)>>>(W_attn, wa_t, Cc, 3 * Cc);
    transpose_conv<<<dim3(Cc / 32, Cc / 32), dim3(32, 8)>>>(W_proj, wp_t, Cc, Cc);

    // 1) QKV GEMM (fp16, A converted inline) -> scatter g_qh/g_kh/g_vh
    {
        dim3 grid(3 * Cc / BNg, Bc * Tc / BMg);
        gemm_h<1, 1><<<grid, 256, SMEM_G>>>(x, wa_t, b_attn, nullptr, Cc, 3 * Cc);
    }
    // 2) FA2 fp16 tensor-core attention -> g_yh
    {
        dim3 grid(Tc / QTile, Bc * NHc);
        attn_h<<<grid, 256, ATTN_SMEM>>>();
    }
    // 3) projection GEMM (fp16) -> out (fp32)
    {
        dim3 grid(Cc / BNg, Bc * Tc / BMg);
        gemm_h<0, 0><<<grid, 256, SMEM_G>>>(yh, wp_t, b_proj, out, Cc, Cc);
    }
}

// round 11
// speedup vs baseline: 1.5226x; 1.5226x over previous
#include <cuda_runtime.h>
#include <cuda_fp16.h>
#include <cstdint>

// Problem constants
#define Bc  4
#define Tc  2048
#define Cc  1024
#define NHc 16
#define HDc 64

// ---------------------------------------------------------------------------
// Scratch (no cudaMalloc allowed)
// ---------------------------------------------------------------------------
__device__ __half g_qh[Bc * NHc * Tc * HDc];   // [B*NH, T, HD]
__device__ __half g_kh[Bc * NHc * Tc * HDc];
__device__ __half g_vh[Bc * NHc * Tc * HDc];
__device__ __half g_yh[Bc * Tc * Cc];          // attention out [B,T,C]
__device__ __half g_wa_th[3 * Cc * Cc];        // W_attn^T [3C, C]
__device__ __half g_wp_th[Cc * Cc];            // W_proj^T [C, C]

__device__ __forceinline__ uint32_t smem_u32(const void* p) {
    uint32_t a;
    asm("{ .reg .u64 t; cvta.to.shared.u64 t, %1; cvt.u32.u64 %0, t; }" : "=r"(a) : "l"(p));
    return a;
}
__device__ __forceinline__ void cp16(uint32_t dst, const void* src) {
    asm volatile("cp.async.cg.shared.global [%0], [%1], 16;" :: "r"(dst), "l"(src));
}
__device__ __forceinline__ void cp_commit() {
    asm volatile("cp.async.commit_group;" ::: "memory");
}
template <int N>
__device__ __forceinline__ void cp_wait() {
    asm volatile("cp.async.wait_group %0;" :: "n"(N) : "memory");
}
__device__ __forceinline__ uint32_t h2u(__half2 h) { return *reinterpret_cast<uint32_t*>(&h); }
__device__ __forceinline__ uint32_t packh(float a, float b) {
    return h2u(__float22half2_rn(make_float2(a, b)));
}

__device__ __forceinline__ void mma_f16(float& d0, float& d1, float& d2, float& d3,
                                        uint32_t a0, uint32_t a1, uint32_t a2, uint32_t a3,
                                        uint32_t b0, uint32_t b1)
{
    asm volatile(
        "mma.sync.aligned.m16n8k16.row.col.f32.f16.f16.f32 "
        "{%0,%1,%2,%3}, {%4,%5,%6,%7}, {%8,%9}, {%0,%1,%2,%3};"
        : "+f"(d0), "+f"(d1), "+f"(d2), "+f"(d3)
        : "r"(a0), "r"(a1), "r"(a2), "r"(a3), "r"(b0), "r"(b1));
}
__device__ __forceinline__ void ldm_x4(uint32_t& r0, uint32_t& r1, uint32_t& r2, uint32_t& r3,
                                       uint32_t addr)
{
    asm volatile("ldmatrix.sync.aligned.m8n8.x4.shared.b16 {%0,%1,%2,%3}, [%4];"
                 : "=r"(r0), "=r"(r1), "=r"(r2), "=r"(r3) : "r"(addr));
}
__device__ __forceinline__ void ldm_x4_t(uint32_t& r0, uint32_t& r1, uint32_t& r2, uint32_t& r3,
                                         uint32_t addr)
{
    asm volatile("ldmatrix.sync.aligned.m8n8.x4.trans.shared.b16 {%0,%1,%2,%3}, [%4];"
                 : "=r"(r0), "=r"(r1), "=r"(r2), "=r"(r3) : "r"(addr));
}

// ---------------------------------------------------------------------------
// fp16 mma GEMM (R9 config — 64x32 warp tiles, 2 CTAs/SM): Out = A@Bt^T + bias.
// BM=BN=128, BK=32, 256 threads. k-paired smem -> single LDS.64 per frag pair.
// CONVA=1: A is fp32, converted inline in the load path.
// SCATTER=1: half epilogue into g_qh/g_kh/g_vh; else fp32 Out.
// ---------------------------------------------------------------------------
constexpr int BMg = 128, BNg = 128;

template <int SCATTER, int CONVA>
__global__ __launch_bounds__(256)
void gemm_h(const void* __restrict__ Avp, const __half* __restrict__ Bt,
            const float* __restrict__ bias, float* __restrict__ Out,
            int K, int N)
{
    __shared__ uint2 As2[2][2][BMg][4];   // [buf][ks][row][c]  16 KB
    __shared__ uint2 Bs2[2][2][BNg][4];   // 16 KB

    const int tid  = threadIdx.x;
    const int lane = tid & 31;
    const int wid  = tid >> 5;
    const int g    = lane >> 2;
    const int c    = lane & 3;
    const int warp_m = (wid & 1) * 64;
    const int warp_n = (wid >> 1) * 32;

    const int row  = tid >> 1;
    const int half = tid & 1;

    const __half* Ah = (const __half*)Avp;
    const float*  Af = (const float*)Avp;
    const size_t arow = (size_t)(blockIdx.y * BMg + row);
    const __half* Bp = Bt + (size_t)(blockIdx.x * BNg + row) * K + half * 16;

    uint4 au, av, bu, bv;
    auto ldg_tile = [&](int k0) {
        if (CONVA) {
            const float* ap = Af + arow * K + half * 16 + k0;
            float4 f0 = *(const float4*)(ap);
            float4 f1 = *(const float4*)(ap + 4);
            float4 f2 = *(const float4*)(ap + 8);
            float4 f3 = *(const float4*)(ap + 12);
            au.x = packh(f0.x, f0.y);  au.y = packh(f0.z, f0.w);
            au.z = packh(f1.x, f1.y);  au.w = packh(f1.z, f1.w);
            av.x = packh(f2.x, f2.y);  av.y = packh(f2.z, f2.w);
            av.z = packh(f3.x, f3.y);  av.w = packh(f3.z, f3.w);
        } else {
            const __half* ap = Ah + arow * K + half * 16 + k0;
            au = *(const uint4*)(ap);
            av = *(const uint4*)(ap + 8);
        }
        bu = *(const uint4*)(Bp + k0);
        bv = *(const uint4*)(Bp + k0 + 8);
    };
    auto sts_tile = [&](int buf) {
        As2[buf][half][row][0] = make_uint2(au.x, av.x);
        As2[buf][half][row][1] = make_uint2(au.y, av.y);
        As2[buf][half][row][2] = make_uint2(au.z, av.z);
        As2[buf][half][row][3] = make_uint2(au.w, av.w);
        Bs2[buf][half][row][0] = make_uint2(bu.x, bv.x);
        Bs2[buf][half][row][1] = make_uint2(bu.y, bv.y);
        Bs2[buf][half][row][2] = make_uint2(bu.z, bv.z);
        Bs2[buf][half][row][3] = make_uint2(bu.w, bv.w);
    };

    float acc[4][4][4];
#pragma unroll
    for (int i = 0; i < 4; i++)
#pragma unroll
        for (int j = 0; j < 4; j++)
#pragma unroll
            for (int r = 0; r < 4; r++) acc[i][j][r] = 0.f;

    const int NT = K / 32;
    ldg_tile(0);
    sts_tile(0);
    __syncthreads();

    for (int kt = 0; kt < NT; kt++) {
        const int buf = kt & 1;
        if (kt + 1 < NT) ldg_tile((kt + 1) * 32);

#pragma unroll
        for (int ks = 0; ks < 2; ks++) {
            uint32_t af[4][4], bf[4][2];
#pragma unroll
            for (int mt = 0; mt < 4; mt++) {
                uint2 lo = As2[buf][ks][warp_m + mt * 16 + g][c];
                uint2 hi = As2[buf][ks][warp_m + mt * 16 + 8 + g][c];
                af[mt][0] = lo.x;  af[mt][1] = hi.x;
                af[mt][2] = lo.y;  af[mt][3] = hi.y;
            }
#pragma unroll
            for (int nt = 0; nt < 4; nt++) {
                uint2 bb = Bs2[buf][ks][warp_n + nt * 8 + g][c];
                bf[nt][0] = bb.x;  bf[nt][1] = bb.y;
            }
#pragma unroll
            for (int mt = 0; mt < 4; mt++)
#pragma unroll
                for (int nt = 0; nt < 4; nt++)
                    mma_f16(acc[mt][nt][0], acc[mt][nt][1], acc[mt][nt][2], acc[mt][nt][3],
                            af[mt][0], af[mt][1], af[mt][2], af[mt][3],
                            bf[nt][0], bf[nt][1]);
        }
        __syncthreads();
        if (kt + 1 < NT) {
            sts_tile(buf ^ 1);
            __syncthreads();
        }
    }

#pragma unroll
    for (int mt = 0; mt < 4; mt++) {
#pragma unroll
        for (int nt = 0; nt < 4; nt++) {
            int n0 = blockIdx.x * BNg + warp_n + nt * 8 + 2 * c;
            float2 bb = *(const float2*)(bias + n0);
            int m0 = blockIdx.y * BMg + warp_m + mt * 16 + g;
#pragma unroll
            for (int rh = 0; rh < 2; rh++) {
                int m = m0 + rh * 8;
                float vx = acc[mt][nt][2 * rh + 0] + bb.x;
                float vy = acc[mt][nt][2 * rh + 1] + bb.y;
                if (SCATTER) {
                    __half2 hv = __float22half2_rn(make_float2(vx, vy));
                    int which = n0 >> 10, c0 = n0 & 1023;
                    int h = c0 >> 6, d = c0 & 63;
                    int b = m >> 11, t = m & 2047;
                    __half* dst = (which == 0) ? g_qh : ((which == 1) ? g_kh : g_vh);
                    *(__half2*)&dst[(((size_t)(b * NHc + h)) * Tc + t) * HDc + d] = hv;
                } else {
                    *(float2*)&Out[(size_t)m * N + n0] = make_float2(vx, vy);
                }
            }
        }
    }
}

// ---------------------------------------------------------------------------
// Prep: transpose + fp32->fp16 for weights
// ---------------------------------------------------------------------------
__global__ void transpose_conv(const float* __restrict__ W, __half* __restrict__ Bt,
                               int K, int N)
{
    __shared__ float t[32][33];
    int n0 = blockIdx.x * 32, k0 = blockIdx.y * 32;
    int tx = threadIdx.x, ty = threadIdx.y;
#pragma unroll
    for (int i = 0; i < 32; i += 8)
        t[ty + i][tx] = W[(size_t)(k0 + ty + i) * N + n0 + tx];
    __syncthreads();
#pragma unroll
    for (int i = 0; i < 32; i += 8)
        Bt[(size_t)(n0 + ty + i) * K + k0 + tx] = __float2half_rn(t[tx][ty + i]);
}

// ---------------------------------------------------------------------------
// FA2 attention, fp16 mma m16n8k16. R9 body + __launch_bounds__(256,2):
// caps regs at 128 -> 2 CTAs/SM (was 132 regs / 1 CTA / occ 12.5%).
// ---------------------------------------------------------------------------
constexpr int QTile = 128;
constexpr int KTile = 64;
constexpr int KVSH  = 72;
constexpr int ATTN_SMEM = 2 * 2 * KTile * KVSH * 2;      // 36864 B

__global__ __launch_bounds__(256, 2)
void attn_h()
{
    extern __shared__ __half smh[];
    __half* KsBase = smh;
    __half* VsBase = smh + 2 * KTile * KVSH;

    const int qt  = (gridDim.x - 1) - blockIdx.x;
    const int bh  = blockIdx.y;
    const int qb  = qt * QTile;
    const int tid = threadIdx.x;
    const int lane = tid & 31;
    const int w   = tid >> 5;
    const int g   = lane >> 2;
    const int c   = lane & 3;

    const __half* gq = g_qh + (size_t)bh * Tc * HDc;
    const __half* gk = g_kh + (size_t)bh * Tc * HDc;
    const __half* gv = g_vh + (size_t)bh * Tc * HDc;

    const int r0 = qb + w * 16 + g;

    const __half2 scl = __float2half2_rn(0.125f);
    const __half2* q0p = (const __half2*)(gq + (size_t)r0 * HDc);
    const __half2* q1p = (const __half2*)(gq + (size_t)(r0 + 8) * HDc);
    uint32_t aq[4][4];
#pragma unroll
    for (int kk = 0; kk < 4; kk++) {
        aq[kk][0] = h2u(__hmul2(q0p[8 * kk + c],     scl));
        aq[kk][1] = h2u(__hmul2(q1p[8 * kk + c],     scl));
        aq[kk][2] = h2u(__hmul2(q0p[8 * kk + c + 4], scl));
        aq[kk][3] = h2u(__hmul2(q1p[8 * kk + c + 4], scl));
    }

    float o[8][4];
#pragma unroll
    for (int nt = 0; nt < 8; nt++)
#pragma unroll
        for (int j = 0; j < 4; j++) o[nt][j] = 0.f;
    float m0 = -1e30f, m1 = -1e30f, l0 = 0.f, l1 = 0.f;

    auto load_kv = [&](int t, int buf) {
        const __half* ksrc = gk + (size_t)t * KTile * HDc;
        const __half* vsrc = gv + (size_t)t * KTile * HDc;
        __half* kd = KsBase + buf * KTile * KVSH;
        __half* vd = VsBase + buf * KTile * KVSH;
#pragma unroll
        for (int i = 0; i < 2; i++) {
            int id = tid + i * 256;
            int row = id >> 3, ch = (id & 7) * 8;
            cp16(smem_u32(kd + row * KVSH + ch), ksrc + row * HDc + ch);
            cp16(smem_u32(vd + row * KVSH + ch), vsrc + row * HDc + ch);
        }
    };

    const int NT = 2 * (qt + 1);
    load_kv(0, 0); cp_commit();

    for (int t = 0; t < NT; t++) {
        const int buf = t & 1;
        if (t + 1 < NT) { load_kv(t + 1, buf ^ 1); cp_commit(); cp_wait<1>(); }
        else            { cp_wait<0>(); }
        __syncthreads();

        const uint32_t ksb = smem_u32(KsBase + buf * KTile * KVSH);
        const uint32_t vsb = smem_u32(VsBase + buf * KTile * KVSH);
        const int kb = t * KTile;

        float s[8][4];
#pragma unroll
        for (int nt = 0; nt < 8; nt++)
#pragma unroll
            for (int j = 0; j < 4; j++) s[nt][j] = 0.f;

#pragma unroll
        for (int nt = 0; nt < 8; nt++) {
            uint32_t k0r, k1r, k2r, k3r;
            uint32_t addr = ksb + (uint32_t)(((nt * 8 + (lane & 7)) * KVSH + (lane >> 3) * 8) * 2);
            ldm_x4(k0r, k1r, k2r, k3r, addr);
            mma_f16(s[nt][0], s[nt][1], s[nt][2], s[nt][3],
                    aq[0][0], aq[0][1], aq[0][2], aq[0][3], k0r, k1r);
            mma_f16(s[nt][0], s[nt][1], s[nt][2], s[nt][3],
                    aq[1][0], aq[1][1], aq[1][2], aq[1][3], k2r, k3r);
            ldm_x4(k0r, k1r, k2r, k3r, addr + 64);
            mma_f16(s[nt][0], s[nt][1], s[nt][2], s[nt][3],
                    aq[2][0], aq[2][1], aq[2][2], aq[2][3], k0r, k1r);
            mma_f16(s[nt][0], s[nt][1], s[nt][2], s[nt][3],
                    aq[3][0], aq[3][1], aq[3][2], aq[3][3], k2r, k3r);
        }

        if (kb + KTile - 1 > qb + w * 16) {
#pragma unroll
            for (int nt = 0; nt < 8; nt++) {
                int key0 = kb + nt * 8 + 2 * c;
                if (key0     > r0)     s[nt][0] = -1e30f;
                if (key0 + 1 > r0)     s[nt][1] = -1e30f;
                if (key0     > r0 + 8) s[nt][2] = -1e30f;
                if (key0 + 1 > r0 + 8) s[nt][3] = -1e30f;
            }
        }

        float rm0 = -1e30f, rm1 = -1e30f;
#pragma unroll
        for (int nt = 0; nt < 8; nt++) {
            rm0 = fmaxf(rm0, fmaxf(s[nt][0], s[nt][1]));
            rm1 = fmaxf(rm1, fmaxf(s[nt][2], s[nt][3]));
        }
        rm0 = fmaxf(rm0, __shfl_xor_sync(0xffffffffu, rm0, 1));
        rm0 = fmaxf(rm0, __shfl_xor_sync(0xffffffffu, rm0, 2));
        rm1 = fmaxf(rm1, __shfl_xor_sync(0xffffffffu, rm1, 1));
        rm1 = fmaxf(rm1, __shfl_xor_sync(0xffffffffu, rm1, 2));

        float mn0 = fmaxf(m0, rm0), mn1 = fmaxf(m1, rm1);
        float corr0 = __expf(m0 - mn0), corr1 = __expf(m1 - mn1);
        m0 = mn0; m1 = mn1;

        float ls0 = 0.f, ls1 = 0.f;
        uint32_t pu0[8], pu1[8];
#pragma unroll
        for (int nt = 0; nt < 8; nt++) {
            float p0 = __expf(s[nt][0] - m0);
            float p1 = __expf(s[nt][1] - m0);
            float p2 = __expf(s[nt][2] - m1);
            float p3 = __expf(s[nt][3] - m1);
            ls0 += p0 + p1;  ls1 += p2 + p3;
            pu0[nt] = packh(p0, p1);
            pu1[nt] = packh(p2, p3);
        }
        ls0 += __shfl_xor_sync(0xffffffffu, ls0, 1);
        ls0 += __shfl_xor_sync(0xffffffffu, ls0, 2);
        ls1 += __shfl_xor_sync(0xffffffffu, ls1, 1);
        ls1 += __shfl_xor_sync(0xffffffffu, ls1, 2);
        l0 = l0 * corr0 + ls0;
        l1 = l1 * corr1 + ls1;
#pragma unroll
        for (int nt = 0; nt < 8; nt++) {
            o[nt][0] *= corr0; o[nt][1] *= corr0;
            o[nt][2] *= corr1; o[nt][3] *= corr1;
        }

#pragma unroll
        for (int kk2 = 0; kk2 < 4; kk2++) {
            uint32_t a0 = pu0[2 * kk2],     a1 = pu1[2 * kk2];
            uint32_t a2 = pu0[2 * kk2 + 1], a3 = pu1[2 * kk2 + 1];
#pragma unroll
            for (int ntp = 0; ntp < 4; ntp++) {
                uint32_t v0, v1, v2, v3;
                uint32_t addr = vsb + (uint32_t)((
                    (kk2 * 16 + ((lane >> 3) & 1) * 8 + (lane & 7)) * KVSH +
                    (2 * ntp + (lane >> 4)) * 8) * 2);
                ldm_x4_t(v0, v1, v2, v3, addr);
                mma_f16(o[2 * ntp][0], o[2 * ntp][1], o[2 * ntp][2], o[2 * ntp][3],
                        a0, a1, a2, a3, v0, v1);
                mma_f16(o[2 * ntp + 1][0], o[2 * ntp + 1][1], o[2 * ntp + 1][2], o[2 * ntp + 1][3],
                        a0, a1, a2, a3, v2, v3);
            }
        }
        __syncthreads();
    }

    float inv0 = 1.f / l0, inv1 = 1.f / l1;
    int b = bh >> 4, h = bh & 15;
    __half* y0 = g_yh + ((size_t)b * Tc + r0) * Cc + h * HDc;
    __half* y1 = y0 + (size_t)8 * Cc;
#pragma unroll
    for (int nt = 0; nt < 8; nt++) {
        *(__half2*)&y0[nt * 8 + 2 * c] =
            __float22half2_rn(make_float2(o[nt][0] * inv0, o[nt][1] * inv0));
        *(__half2*)&y1[nt * 8 + 2 * c] =
            __float22half2_rn(make_float2(o[nt][2] * inv1, o[nt][3] * inv1));
    }
}

// ---------------------------------------------------------------------------
// Launch
// ---------------------------------------------------------------------------
extern "C" void kernel_launch(void* const* d_in, const int* in_sizes, int n_in,
                              void* d_out, int out_size)
{
    const float* x      = (const float*)d_in[0];
    const float* W_attn = (const float*)d_in[1];
    const float* b_attn = (const float*)d_in[2];
    const float* W_proj = (const float*)d_in[3];
    const float* b_proj = (const float*)d_in[4];
    float* out = (float*)d_out;

    __half *yh, *wa_t, *wp_t;
    cudaGetSymbolAddress((void**)&yh,   g_yh);
    cudaGetSymbolAddress((void**)&wa_t, g_wa_th);
    cudaGetSymbolAddress((void**)&wp_t, g_wp_th);

    static bool attr_done = false;
    if (!attr_done) {
        cudaFuncSetAttribute(attn_h, cudaFuncAttributeMaxDynamicSharedMemorySize, ATTN_SMEM);
        attr_done = true;
    }

    // Prep: transpose+convert weights (x conversion folded into GEMM1 loads)
    transpose_conv<<<dim3(3 * Cc / 32, Cc / 32), dim3(32, 8)>>>(W_attn, wa_t, Cc, 3 * Cc);
    transpose_conv<<<dim3(Cc / 32, Cc / 32), dim3(32, 8)>>>(W_proj, wp_t, Cc, Cc);

    // 1) QKV GEMM (fp16, A converted inline) -> scatter g_qh/g_kh/g_vh
    {
        dim3 grid(3 * Cc / BNg, Bc * Tc / BMg);
        gemm_h<1, 1><<<grid, 256>>>(x, wa_t, b_attn, nullptr, Cc, 3 * Cc);
    }
    // 2) FA2 fp16 tensor-core attention -> g_yh
    {
        dim3 grid(Tc / QTile, Bc * NHc);
        attn_h<<<grid, 256, ATTN_SMEM>>>();
    }
    // 3) projection GEMM (fp16) -> out (fp32)
    {
        dim3 grid(Cc / BNg, Bc * Tc / BMg);
        gemm_h<0, 0><<<grid, 256>>>(yh, wp_t, b_proj, out, Cc, Cc);
    }
}

// round 12
// speedup vs baseline: 2.0071x; 1.3182x over previous
#include <cuda_runtime.h>
#include <cuda_fp16.h>
#include <cstdint>

// Problem constants
#define Bc  4
#define Tc  2048
#define Cc  1024
#define NHc 16
#define HDc 64

// ---------------------------------------------------------------------------
// Scratch (no cudaMalloc allowed)
// ---------------------------------------------------------------------------
__device__ __half g_qh[Bc * NHc * Tc * HDc];   // [B*NH, T, HD]
__device__ __half g_kh[Bc * NHc * Tc * HDc];
__device__ __half g_vh[Bc * NHc * Tc * HDc];
__device__ __half g_yh[Bc * Tc * Cc];          // attention out [B,T,C]
__device__ __half g_xh[Bc * Tc * Cc];          // fp16 x
__device__ __half g_wa_th[3 * Cc * Cc];        // W_attn^T [3C, C]
__device__ __half g_wp_th[Cc * Cc];            // W_proj^T [C, C]

__device__ __forceinline__ uint32_t smem_u32(const void* p) {
    uint32_t a;
    asm("{ .reg .u64 t; cvta.to.shared.u64 t, %1; cvt.u32.u64 %0, t; }" : "=r"(a) : "l"(p));
    return a;
}
__device__ __forceinline__ void cp16(uint32_t dst, const void* src) {
    asm volatile("cp.async.cg.shared.global [%0], [%1], 16;" :: "r"(dst), "l"(src));
}
__device__ __forceinline__ void cp_commit() {
    asm volatile("cp.async.commit_group;" ::: "memory");
}
template <int N>
__device__ __forceinline__ void cp_wait() {
    asm volatile("cp.async.wait_group %0;" :: "n"(N) : "memory");
}
__device__ __forceinline__ uint32_t h2u(__half2 h) { return *reinterpret_cast<uint32_t*>(&h); }
__device__ __forceinline__ uint32_t packh(float a, float b) {
    return h2u(__float22half2_rn(make_float2(a, b)));
}

__device__ __forceinline__ void mma_f16(float& d0, float& d1, float& d2, float& d3,
                                        uint32_t a0, uint32_t a1, uint32_t a2, uint32_t a3,
                                        uint32_t b0, uint32_t b1)
{
    asm volatile(
        "mma.sync.aligned.m16n8k16.row.col.f32.f16.f16.f32 "
        "{%0,%1,%2,%3}, {%4,%5,%6,%7}, {%8,%9}, {%0,%1,%2,%3};"
        : "+f"(d0), "+f"(d1), "+f"(d2), "+f"(d3)
        : "r"(a0), "r"(a1), "r"(a2), "r"(a3), "r"(b0), "r"(b1));
}
__device__ __forceinline__ void ldm_x4(uint32_t& r0, uint32_t& r1, uint32_t& r2, uint32_t& r3,
                                       uint32_t addr)
{
    asm volatile("ldmatrix.sync.aligned.m8n8.x4.shared.b16 {%0,%1,%2,%3}, [%4];"
                 : "=r"(r0), "=r"(r1), "=r"(r2), "=r"(r3) : "r"(addr));
}
__device__ __forceinline__ void ldm_x4_t(uint32_t& r0, uint32_t& r1, uint32_t& r2, uint32_t& r3,
                                         uint32_t addr)
{
    asm volatile("ldmatrix.sync.aligned.m8n8.x4.trans.shared.b16 {%0,%1,%2,%3}, [%4];"
                 : "=r"(r0), "=r"(r1), "=r"(r2), "=r"(r3) : "r"(addr));
}

// ---------------------------------------------------------------------------
// fp16 mma GEMM: Out[M,N] = A[M,K]@Bt[N,K]^T + bias.
// BM=BN=128, BK=32, 256 threads, 64x32 warp tiles.
// NEW: cp.async 3-stage pipeline (1 barrier/k-tile) + ldmatrix.x4 fragments.
// Rows stored contiguously, GST=40-half stride (80B -> 5-granule shift/row,
// conflict-free for both cp.async stores and ldmatrix reads).
// SCATTER=1: half epilogue into g_qh/g_kh/g_vh; else fp32 Out.
// ---------------------------------------------------------------------------
constexpr int BMg = 128, BNg = 128;
constexpr int GST = 40;                                 // halves per smem row
constexpr int STAGE_HALVES = (BMg + BNg) * GST;         // 10240 halves / stage
constexpr int GEMM_SMEM = 3 * STAGE_HALVES * 2;         // 61440 B

template <int SCATTER>
__global__ __launch_bounds__(256, 2)
void gemm_h(const __half* __restrict__ A, const __half* __restrict__ Bt,
            const float* __restrict__ bias, float* __restrict__ Out,
            int K, int N)
{
    extern __shared__ __half sg[];

    const int tid  = threadIdx.x;
    const int lane = tid & 31;
    const int wid  = tid >> 5;
    const int g    = lane >> 2;
    const int c    = lane & 3;
    const int warp_m = (wid & 1) * 64;
    const int warp_n = (wid >> 1) * 32;
    const int lrow = lane & 15;          // ldmatrix row within 16-row group
    const int lcol = (lane >> 4) * 8;    // ldmatrix 16B col select (halves)

    const __half* Asrc0 = A  + (size_t)blockIdx.y * BMg * K;
    const __half* Bsrc0 = Bt + (size_t)blockIdx.x * BNg * K;

    auto load_stage = [&](int kt, int st) {
        __half* sA = sg + st * STAGE_HALVES;
        __half* sB = sA + BMg * GST;
        const __half* Asrc = Asrc0 + kt * 32;
        const __half* Bsrc = Bsrc0 + kt * 32;
#pragma unroll
        for (int i = 0; i < 2; i++) {
            int ch = tid + i * 256;          // 0..511
            int row = ch >> 2, q = (ch & 3) * 8;
            cp16(smem_u32(sA + row * GST + q), Asrc + (size_t)row * K + q);
            cp16(smem_u32(sB + row * GST + q), Bsrc + (size_t)row * K + q);
        }
    };

    float acc[4][4][4];
#pragma unroll
    for (int i = 0; i < 4; i++)
#pragma unroll
        for (int j = 0; j < 4; j++)
#pragma unroll
            for (int r = 0; r < 4; r++) acc[i][j][r] = 0.f;

    const int NT = K / 32;
    load_stage(0, 0); cp_commit();
    load_stage(1, 1); cp_commit();

    int st = 0;
    for (int kt = 0; kt < NT; kt++) {
        if (kt + 1 < NT) cp_wait<1>(); else cp_wait<0>();
        __syncthreads();

        const uint32_t sAu = smem_u32(sg + st * STAGE_HALVES);
        const uint32_t sBu = sAu + BMg * GST * 2;

#pragma unroll
        for (int ks = 0; ks < 2; ks++) {
            uint32_t af[4][4], bf[4][2];
#pragma unroll
            for (int mt = 0; mt < 4; mt++) {
                uint32_t addr = sAu + (uint32_t)(((warp_m + mt * 16 + lrow) * GST
                                                 + ks * 16 + lcol) * 2);
                ldm_x4(af[mt][0], af[mt][1], af[mt][2], af[mt][3], addr);
            }
#pragma unroll
            for (int bp = 0; bp < 2; bp++) {
                uint32_t addr = sBu + (uint32_t)(((warp_n + bp * 16 + lrow) * GST
                                                 + ks * 16 + lcol) * 2);
                ldm_x4(bf[2 * bp][0], bf[2 * bp + 1][0],
                       bf[2 * bp][1], bf[2 * bp + 1][1], addr);
            }
#pragma unroll
            for (int mt = 0; mt < 4; mt++)
#pragma unroll
                for (int nt = 0; nt < 4; nt++)
                    mma_f16(acc[mt][nt][0], acc[mt][nt][1], acc[mt][nt][2], acc[mt][nt][3],
                            af[mt][0], af[mt][1], af[mt][2], af[mt][3],
                            bf[nt][0], bf[nt][1]);
        }

        if (kt + 2 < NT) {
            int s2 = st + 2; if (s2 >= 3) s2 -= 3;
            load_stage(kt + 2, s2);
            cp_commit();
        }
        if (++st == 3) st = 0;
    }

    // Epilogue: acc -> global (+bias)
#pragma unroll
    for (int mt = 0; mt < 4; mt++) {
#pragma unroll
        for (int nt = 0; nt < 4; nt++) {
            int n0 = blockIdx.x * BNg + warp_n + nt * 8 + 2 * c;
            float2 bb = *(const float2*)(bias + n0);
            int m0 = blockIdx.y * BMg + warp_m + mt * 16 + g;
#pragma unroll
            for (int rh = 0; rh < 2; rh++) {
                int m = m0 + rh * 8;
                float vx = acc[mt][nt][2 * rh + 0] + bb.x;
                float vy = acc[mt][nt][2 * rh + 1] + bb.y;
                if (SCATTER) {
                    __half2 hv = __float22half2_rn(make_float2(vx, vy));
                    int which = n0 >> 10, c0 = n0 & 1023;
                    int h = c0 >> 6, d = c0 & 63;
                    int b = m >> 11, t = m & 2047;
                    __half* dst = (which == 0) ? g_qh : ((which == 1) ? g_kh : g_vh);
                    *(__half2*)&dst[(((size_t)(b * NHc + h)) * Tc + t) * HDc + d] = hv;
                } else {
                    *(float2*)&Out[(size_t)m * N + n0] = make_float2(vx, vy);
                }
            }
        }
    }
}

// ---------------------------------------------------------------------------
// Prep kernels
// ---------------------------------------------------------------------------
__global__ void conv_x_kernel(const float* __restrict__ x, int n4)
{
    int i = blockIdx.x * blockDim.x + threadIdx.x;
    if (i < n4) {
        float4 v = ((const float4*)x)[i];
        ((__half2*)g_xh)[2 * i]     = __float22half2_rn(make_float2(v.x, v.y));
        ((__half2*)g_xh)[2 * i + 1] = __float22half2_rn(make_float2(v.z, v.w));
    }
}

__global__ void transpose_conv(const float* __restrict__ W, __half* __restrict__ Bt,
                               int K, int N)
{
    __shared__ float t[32][33];
    int n0 = blockIdx.x * 32, k0 = blockIdx.y * 32;
    int tx = threadIdx.x, ty = threadIdx.y;
#pragma unroll
    for (int i = 0; i < 32; i += 8)
        t[ty + i][tx] = W[(size_t)(k0 + ty + i) * N + n0 + tx];
    __syncthreads();
#pragma unroll
    for (int i = 0; i < 32; i += 8)
        Bt[(size_t)(n0 + ty + i) * K + k0 + tx] = __float2half_rn(t[tx][ty + i]);
}

// ---------------------------------------------------------------------------
// FA2 attention, fp16 mma m16n8k16 (R11 — 163.5us, occ 23.4%). Unchanged.
// ---------------------------------------------------------------------------
constexpr int QTile = 128;
constexpr int KTile = 64;
constexpr int KVSH  = 72;
constexpr int ATTN_SMEM = 2 * 2 * KTile * KVSH * 2;      // 36864 B

__global__ __launch_bounds__(256, 2)
void attn_h()
{
    extern __shared__ __half smh[];
    __half* KsBase = smh;
    __half* VsBase = smh + 2 * KTile * KVSH;

    const int qt  = (gridDim.x - 1) - blockIdx.x;
    const int bh  = blockIdx.y;
    const int qb  = qt * QTile;
    const int tid = threadIdx.x;
    const int lane = tid & 31;
    const int w   = tid >> 5;
    const int g   = lane >> 2;
    const int c   = lane & 3;

    const __half* gq = g_qh + (size_t)bh * Tc * HDc;
    const __half* gk = g_kh + (size_t)bh * Tc * HDc;
    const __half* gv = g_vh + (size_t)bh * Tc * HDc;

    const int r0 = qb + w * 16 + g;

    const __half2 scl = __float2half2_rn(0.125f);
    const __half2* q0p = (const __half2*)(gq + (size_t)r0 * HDc);
    const __half2* q1p = (const __half2*)(gq + (size_t)(r0 + 8) * HDc);
    uint32_t aq[4][4];
#pragma unroll
    for (int kk = 0; kk < 4; kk++) {
        aq[kk][0] = h2u(__hmul2(q0p[8 * kk + c],     scl));
        aq[kk][1] = h2u(__hmul2(q1p[8 * kk + c],     scl));
        aq[kk][2] = h2u(__hmul2(q0p[8 * kk + c + 4], scl));
        aq[kk][3] = h2u(__hmul2(q1p[8 * kk + c + 4], scl));
    }

    float o[8][4];
#pragma unroll
    for (int nt = 0; nt < 8; nt++)
#pragma unroll
        for (int j = 0; j < 4; j++) o[nt][j] = 0.f;
    float m0 = -1e30f, m1 = -1e30f, l0 = 0.f, l1 = 0.f;

    auto load_kv = [&](int t, int buf) {
        const __half* ksrc = gk + (size_t)t * KTile * HDc;
        const __half* vsrc = gv + (size_t)t * KTile * HDc;
        __half* kd = KsBase + buf * KTile * KVSH;
        __half* vd = VsBase + buf * KTile * KVSH;
#pragma unroll
        for (int i = 0; i < 2; i++) {
            int id = tid + i * 256;
            int row = id >> 3, ch = (id & 7) * 8;
            cp16(smem_u32(kd + row * KVSH + ch), ksrc + row * HDc + ch);
            cp16(smem_u32(vd + row * KVSH + ch), vsrc + row * HDc + ch);
        }
    };

    const int NT = 2 * (qt + 1);
    load_kv(0, 0); cp_commit();

    for (int t = 0; t < NT; t++) {
        const int buf = t & 1;
        if (t + 1 < NT) { load_kv(t + 1, buf ^ 1); cp_commit(); cp_wait<1>(); }
        else            { cp_wait<0>(); }
        __syncthreads();

        const uint32_t ksb = smem_u32(KsBase + buf * KTile * KVSH);
        const uint32_t vsb = smem_u32(VsBase + buf * KTile * KVSH);
        const int kb = t * KTile;

        float s[8][4];
#pragma unroll
        for (int nt = 0; nt < 8; nt++)
#pragma unroll
            for (int j = 0; j < 4; j++) s[nt][j] = 0.f;

#pragma unroll
        for (int nt = 0; nt < 8; nt++) {
            uint32_t k0r, k1r, k2r, k3r;
            uint32_t addr = ksb + (uint32_t)(((nt * 8 + (lane & 7)) * KVSH + (lane >> 3) * 8) * 2);
            ldm_x4(k0r, k1r, k2r, k3r, addr);
            mma_f16(s[nt][0], s[nt][1], s[nt][2], s[nt][3],
                    aq[0][0], aq[0][1], aq[0][2], aq[0][3], k0r, k1r);
            mma_f16(s[nt][0], s[nt][1], s[nt][2], s[nt][3],
                    aq[1][0], aq[1][1], aq[1][2], aq[1][3], k2r, k3r);
            ldm_x4(k0r, k1r, k2r, k3r, addr + 64);
            mma_f16(s[nt][0], s[nt][1], s[nt][2], s[nt][3],
                    aq[2][0], aq[2][1], aq[2][2], aq[2][3], k0r, k1r);
            mma_f16(s[nt][0], s[nt][1], s[nt][2], s[nt][3],
                    aq[3][0], aq[3][1], aq[3][2], aq[3][3], k2r, k3r);
        }

        if (kb + KTile - 1 > qb + w * 16) {
#pragma unroll
            for (int nt = 0; nt < 8; nt++) {
                int key0 = kb + nt * 8 + 2 * c;
                if (key0     > r0)     s[nt][0] = -1e30f;
                if (key0 + 1 > r0)     s[nt][1] = -1e30f;
                if (key0     > r0 + 8) s[nt][2] = -1e30f;
                if (key0 + 1 > r0 + 8) s[nt][3] = -1e30f;
            }
        }

        float rm0 = -1e30f, rm1 = -1e30f;
#pragma unroll
        for (int nt = 0; nt < 8; nt++) {
            rm0 = fmaxf(rm0, fmaxf(s[nt][0], s[nt][1]));
            rm1 = fmaxf(rm1, fmaxf(s[nt][2], s[nt][3]));
        }
        rm0 = fmaxf(rm0, __shfl_xor_sync(0xffffffffu, rm0, 1));
        rm0 = fmaxf(rm0, __shfl_xor_sync(0xffffffffu, rm0, 2));
        rm1 = fmaxf(rm1, __shfl_xor_sync(0xffffffffu, rm1, 1));
        rm1 = fmaxf(rm1, __shfl_xor_sync(0xffffffffu, rm1, 2));

        float mn0 = fmaxf(m0, rm0), mn1 = fmaxf(m1, rm1);
        float corr0 = __expf(m0 - mn0), corr1 = __expf(m1 - mn1);
        m0 = mn0; m1 = mn1;

        float ls0 = 0.f, ls1 = 0.f;
        uint32_t pu0[8], pu1[8];
#pragma unroll
        for (int nt = 0; nt < 8; nt++) {
            float p0 = __expf(s[nt][0] - m0);
            float p1 = __expf(s[nt][1] - m0);
            float p2 = __expf(s[nt][2] - m1);
            float p3 = __expf(s[nt][3] - m1);
            ls0 += p0 + p1;  ls1 += p2 + p3;
            pu0[nt] = packh(p0, p1);
            pu1[nt] = packh(p2, p3);
        }
        ls0 += __shfl_xor_sync(0xffffffffu, ls0, 1);
        ls0 += __shfl_xor_sync(0xffffffffu, ls0, 2);
        ls1 += __shfl_xor_sync(0xffffffffu, ls1, 1);
        ls1 += __shfl_xor_sync(0xffffffffu, ls1, 2);
        l0 = l0 * corr0 + ls0;
        l1 = l1 * corr1 + ls1;
#pragma unroll
        for (int nt = 0; nt < 8; nt++) {
            o[nt][0] *= corr0; o[nt][1] *= corr0;
            o[nt][2] *= corr1; o[nt][3] *= corr1;
        }

#pragma unroll
        for (int kk2 = 0; kk2 < 4; kk2++) {
            uint32_t a0 = pu0[2 * kk2],     a1 = pu1[2 * kk2];
            uint32_t a2 = pu0[2 * kk2 + 1], a3 = pu1[2 * kk2 + 1];
#pragma unroll
            for (int ntp = 0; ntp < 4; ntp++) {
                uint32_t v0, v1, v2, v3;
                uint32_t addr = vsb + (uint32_t)((
                    (kk2 * 16 + ((lane >> 3) & 1) * 8 + (lane & 7)) * KVSH +
                    (2 * ntp + (lane >> 4)) * 8) * 2);
                ldm_x4_t(v0, v1, v2, v3, addr);
                mma_f16(o[2 * ntp][0], o[2 * ntp][1], o[2 * ntp][2], o[2 * ntp][3],
                        a0, a1, a2, a3, v0, v1);
                mma_f16(o[2 * ntp + 1][0], o[2 * ntp + 1][1], o[2 * ntp + 1][2], o[2 * ntp + 1][3],
                        a0, a1, a2, a3, v2, v3);
            }
        }
        __syncthreads();
    }

    float inv0 = 1.f / l0, inv1 = 1.f / l1;
    int b = bh >> 4, h = bh & 15;
    __half* y0 = g_yh + ((size_t)b * Tc + r0) * Cc + h * HDc;
    __half* y1 = y0 + (size_t)8 * Cc;
#pragma unroll
    for (int nt = 0; nt < 8; nt++) {
        *(__half2*)&y0[nt * 8 + 2 * c] =
            __float22half2_rn(make_float2(o[nt][0] * inv0, o[nt][1] * inv0));
        *(__half2*)&y1[nt * 8 + 2 * c] =
            __float22half2_rn(make_float2(o[nt][2] * inv1, o[nt][3] * inv1));
    }
}

// ---------------------------------------------------------------------------
// Launch
// ---------------------------------------------------------------------------
extern "C" void kernel_launch(void* const* d_in, const int* in_sizes, int n_in,
                              void* d_out, int out_size)
{
    const float* x      = (const float*)d_in[0];
    const float* W_attn = (const float*)d_in[1];
    const float* b_attn = (const float*)d_in[2];
    const float* W_proj = (const float*)d_in[3];
    const float* b_proj = (const float*)d_in[4];
    float* out = (float*)d_out;

    __half *xh, *yh, *wa_t, *wp_t;
    cudaGetSymbolAddress((void**)&xh,   g_xh);
    cudaGetSymbolAddress((void**)&yh,   g_yh);
    cudaGetSymbolAddress((void**)&wa_t, g_wa_th);
    cudaGetSymbolAddress((void**)&wp_t, g_wp_th);

    static bool attr_done = false;
    if (!attr_done) {
        cudaFuncSetAttribute(gemm_h<1>, cudaFuncAttributeMaxDynamicSharedMemorySize, GEMM_SMEM);
        cudaFuncSetAttribute(gemm_h<0>, cudaFuncAttributeMaxDynamicSharedMemorySize, GEMM_SMEM);
        cudaFuncSetAttribute(attn_h, cudaFuncAttributeMaxDynamicSharedMemorySize, ATTN_SMEM);
        attr_done = true;
    }

    // Prep: x -> fp16 once; transpose+convert weights
    {
        int n4 = Bc * Tc * Cc / 4;
        conv_x_kernel<<<(n4 + 255) / 256, 256>>>(x, n4);
        transpose_conv<<<dim3(3 * Cc / 32, Cc / 32), dim3(32, 8)>>>(W_attn, wa_t, Cc, 3 * Cc);
        transpose_conv<<<dim3(Cc / 32, Cc / 32), dim3(32, 8)>>>(W_proj, wp_t, Cc, Cc);
    }
    // 1) QKV GEMM (fp16, cp.async 3-stage + ldmatrix) -> scatter g_qh/g_kh/g_vh
    {
        dim3 grid(3 * Cc / BNg, Bc * Tc / BMg);
        gemm_h<1><<<grid, 256, GEMM_SMEM>>>(xh, wa_t, b_attn, nullptr, Cc, 3 * Cc);
    }
    // 2) FA2 fp16 tensor-core attention -> g_yh
    {
        dim3 grid(Tc / QTile, Bc * NHc);
        attn_h<<<grid, 256, ATTN_SMEM>>>();
    }
    // 3) projection GEMM (fp16) -> out (fp32)
    {
        dim3 grid(Cc / BNg, Bc * Tc / BMg);
        gemm_h<0><<<grid, 256, GEMM_SMEM>>>(yh, wp_t, b_proj, out, Cc, Cc);
    }
}

// round 13
// speedup vs baseline: 2.1562x; 1.0743x over previous
#include <cuda_runtime.h>
#include <cuda_fp16.h>
#include <cstdint>

// Problem constants
#define Bc  4
#define Tc  2048
#define Cc  1024
#define NHc 16
#define HDc 64

// ---------------------------------------------------------------------------
// Scratch (no cudaMalloc allowed)
// ---------------------------------------------------------------------------
__device__ __half g_qh[Bc * NHc * Tc * HDc];   // [B*NH, T, HD]
__device__ __half g_kh[Bc * NHc * Tc * HDc];
__device__ __half g_vh[Bc * NHc * Tc * HDc];
__device__ __half g_yh[Bc * Tc * Cc];          // attention out [B,T,C]
__device__ __half g_xh[Bc * Tc * Cc];          // fp16 x
__device__ __half g_wa_th[3 * Cc * Cc];        // W_attn^T [3C, C]
__device__ __half g_wp_th[Cc * Cc];            // W_proj^T [C, C]

__device__ __forceinline__ uint32_t smem_u32(const void* p) {
    uint32_t a;
    asm("{ .reg .u64 t; cvta.to.shared.u64 t, %1; cvt.u32.u64 %0, t; }" : "=r"(a) : "l"(p));
    return a;
}
__device__ __forceinline__ void cp16(uint32_t dst, const void* src) {
    asm volatile("cp.async.cg.shared.global [%0], [%1], 16;" :: "r"(dst), "l"(src));
}
__device__ __forceinline__ void cp_commit() {
    asm volatile("cp.async.commit_group;" ::: "memory");
}
template <int N>
__device__ __forceinline__ void cp_wait() {
    asm volatile("cp.async.wait_group %0;" :: "n"(N) : "memory");
}
__device__ __forceinline__ uint32_t h2u(__half2 h) { return *reinterpret_cast<uint32_t*>(&h); }
__device__ __forceinline__ uint32_t packh(float a, float b) {
    return h2u(__float22half2_rn(make_float2(a, b)));
}

__device__ __forceinline__ void mma_f16(float& d0, float& d1, float& d2, float& d3,
                                        uint32_t a0, uint32_t a1, uint32_t a2, uint32_t a3,
                                        uint32_t b0, uint32_t b1)
{
    asm volatile(
        "mma.sync.aligned.m16n8k16.row.col.f32.f16.f16.f32 "
        "{%0,%1,%2,%3}, {%4,%5,%6,%7}, {%8,%9}, {%0,%1,%2,%3};"
        : "+f"(d0), "+f"(d1), "+f"(d2), "+f"(d3)
        : "r"(a0), "r"(a1), "r"(a2), "r"(a3), "r"(b0), "r"(b1));
}
__device__ __forceinline__ void ldm_x4(uint32_t& r0, uint32_t& r1, uint32_t& r2, uint32_t& r3,
                                       uint32_t addr)
{
    asm volatile("ldmatrix.sync.aligned.m8n8.x4.shared.b16 {%0,%1,%2,%3}, [%4];"
                 : "=r"(r0), "=r"(r1), "=r"(r2), "=r"(r3) : "r"(addr));
}
__device__ __forceinline__ void ldm_x4_t(uint32_t& r0, uint32_t& r1, uint32_t& r2, uint32_t& r3,
                                         uint32_t addr)
{
    asm volatile("ldmatrix.sync.aligned.m8n8.x4.trans.shared.b16 {%0,%1,%2,%3}, [%4];"
                 : "=r"(r0), "=r"(r1), "=r"(r2), "=r"(r3) : "r"(addr));
}

// ---------------------------------------------------------------------------
// fp16 mma GEMM: Out[M,N] = A[M,K]@Bt[N,K]^T + bias.
// BM=BN=128, BK=64 (4 ks-steps / barrier), 256 threads, 64x32 warp tiles.
// cp.async 3-stage pipeline + ldmatrix.x4 fragments.
// Row stride GST=72 halves (144B = 9 granules, odd -> conflict-free).
// SCATTER=1: half epilogue into g_qh/g_kh/g_vh; else fp32 Out.
// ---------------------------------------------------------------------------
constexpr int BMg = 128, BNg = 128, BKg = 64;
constexpr int GST = 72;                                 // halves per smem row
constexpr int STAGE_HALVES = (BMg + BNg) * GST;         // 18432 halves / stage
constexpr int GEMM_SMEM = 3 * STAGE_HALVES * 2;         // 110592 B

template <int SCATTER>
__global__ __launch_bounds__(256, 2)
void gemm_h(const __half* __restrict__ A, const __half* __restrict__ Bt,
            const float* __restrict__ bias, float* __restrict__ Out,
            int K, int N)
{
    extern __shared__ __half sg[];

    const int tid  = threadIdx.x;
    const int lane = tid & 31;
    const int wid  = tid >> 5;
    const int g    = lane >> 2;
    const int c    = lane & 3;
    const int warp_m = (wid & 1) * 64;
    const int warp_n = (wid >> 1) * 32;
    const int lrow = lane & 15;          // ldmatrix row within 16-row group
    const int lcol = (lane >> 4) * 8;    // ldmatrix 16B col select (halves)

    const __half* Asrc0 = A  + (size_t)blockIdx.y * BMg * K;
    const __half* Bsrc0 = Bt + (size_t)blockIdx.x * BNg * K;

    auto load_stage = [&](int kt, int st) {
        __half* sA = sg + st * STAGE_HALVES;
        __half* sB = sA + BMg * GST;
        const __half* Asrc = Asrc0 + kt * BKg;
        const __half* Bsrc = Bsrc0 + kt * BKg;
#pragma unroll
        for (int i = 0; i < 4; i++) {
            int ch = tid + i * 256;          // 0..1023
            int row = ch >> 3, q = (ch & 7) * 8;
            cp16(smem_u32(sA + row * GST + q), Asrc + (size_t)row * K + q);
            cp16(smem_u32(sB + row * GST + q), Bsrc + (size_t)row * K + q);
        }
    };

    float acc[4][4][4];
#pragma unroll
    for (int i = 0; i < 4; i++)
#pragma unroll
        for (int j = 0; j < 4; j++)
#pragma unroll
            for (int r = 0; r < 4; r++) acc[i][j][r] = 0.f;

    const int NT = K / BKg;
    load_stage(0, 0); cp_commit();
    load_stage(1, 1); cp_commit();

    int st = 0;
    for (int kt = 0; kt < NT; kt++) {
        if (kt + 1 < NT) cp_wait<1>(); else cp_wait<0>();
        __syncthreads();

        const uint32_t sAu = smem_u32(sg + st * STAGE_HALVES);
        const uint32_t sBu = sAu + BMg * GST * 2;

#pragma unroll
        for (int ks = 0; ks < 4; ks++) {
            uint32_t af[4][4], bf[4][2];
#pragma unroll
            for (int mt = 0; mt < 4; mt++) {
                uint32_t addr = sAu + (uint32_t)(((warp_m + mt * 16 + lrow) * GST
                                                 + ks * 16 + lcol) * 2);
                ldm_x4(af[mt][0], af[mt][1], af[mt][2], af[mt][3], addr);
            }
#pragma unroll
            for (int bp = 0; bp < 2; bp++) {
                uint32_t addr = sBu + (uint32_t)(((warp_n + bp * 16 + lrow) * GST
                                                 + ks * 16 + lcol) * 2);
                ldm_x4(bf[2 * bp][0], bf[2 * bp + 1][0],
                       bf[2 * bp][1], bf[2 * bp + 1][1], addr);
            }
#pragma unroll
            for (int mt = 0; mt < 4; mt++)
#pragma unroll
                for (int nt = 0; nt < 4; nt++)
                    mma_f16(acc[mt][nt][0], acc[mt][nt][1], acc[mt][nt][2], acc[mt][nt][3],
                            af[mt][0], af[mt][1], af[mt][2], af[mt][3],
                            bf[nt][0], bf[nt][1]);
        }

        if (kt + 2 < NT) {
            int s2 = st + 2; if (s2 >= 3) s2 -= 3;
            load_stage(kt + 2, s2);
            cp_commit();
        }
        if (++st == 3) st = 0;
    }

    // Epilogue: acc -> global (+bias)
#pragma unroll
    for (int mt = 0; mt < 4; mt++) {
#pragma unroll
        for (int nt = 0; nt < 4; nt++) {
            int n0 = blockIdx.x * BNg + warp_n + nt * 8 + 2 * c;
            float2 bb = *(const float2*)(bias + n0);
            int m0 = blockIdx.y * BMg + warp_m + mt * 16 + g;
#pragma unroll
            for (int rh = 0; rh < 2; rh++) {
                int m = m0 + rh * 8;
                float vx = acc[mt][nt][2 * rh + 0] + bb.x;
                float vy = acc[mt][nt][2 * rh + 1] + bb.y;
                if (SCATTER) {
                    __half2 hv = __float22half2_rn(make_float2(vx, vy));
                    int which = n0 >> 10, c0 = n0 & 1023;
                    int h = c0 >> 6, d = c0 & 63;
                    int b = m >> 11, t = m & 2047;
                    __half* dst = (which == 0) ? g_qh : ((which == 1) ? g_kh : g_vh);
                    *(__half2*)&dst[(((size_t)(b * NHc + h)) * Tc + t) * HDc + d] = hv;
                } else {
                    *(float2*)&Out[(size_t)m * N + n0] = make_float2(vx, vy);
                }
            }
        }
    }
}

// ---------------------------------------------------------------------------
// Prep kernels
// ---------------------------------------------------------------------------
__global__ void conv_x_kernel(const float* __restrict__ x, int n4)
{
    int i = blockIdx.x * blockDim.x + threadIdx.x;
    if (i < n4) {
        float4 v = ((const float4*)x)[i];
        ((__half2*)g_xh)[2 * i]     = __float22half2_rn(make_float2(v.x, v.y));
        ((__half2*)g_xh)[2 * i + 1] = __float22half2_rn(make_float2(v.z, v.w));
    }
}

__global__ void transpose_conv(const float* __restrict__ W, __half* __restrict__ Bt,
                               int K, int N)
{
    __shared__ float t[32][33];
    int n0 = blockIdx.x * 32, k0 = blockIdx.y * 32;
    int tx = threadIdx.x, ty = threadIdx.y;
#pragma unroll
    for (int i = 0; i < 32; i += 8)
        t[ty + i][tx] = W[(size_t)(k0 + ty + i) * N + n0 + tx];
    __syncthreads();
#pragma unroll
    for (int i = 0; i < 32; i += 8)
        Bt[(size_t)(n0 + ty + i) * K + k0 + tx] = __float2half_rn(t[tx][ty + i]);
}

// ---------------------------------------------------------------------------
// FA2 attention, fp16 mma m16n8k16 (R11 — 163.5us, occ 23.4%). Unchanged.
// ---------------------------------------------------------------------------
constexpr int QTile = 128;
constexpr int KTile = 64;
constexpr int KVSH  = 72;
constexpr int ATTN_SMEM = 2 * 2 * KTile * KVSH * 2;      // 36864 B

__global__ __launch_bounds__(256, 2)
void attn_h()
{
    extern __shared__ __half smh[];
    __half* KsBase = smh;
    __half* VsBase = smh + 2 * KTile * KVSH;

    const int qt  = (gridDim.x - 1) - blockIdx.x;
    const int bh  = blockIdx.y;
    const int qb  = qt * QTile;
    const int tid = threadIdx.x;
    const int lane = tid & 31;
    const int w   = tid >> 5;
    const int g   = lane >> 2;
    const int c   = lane & 3;

    const __half* gq = g_qh + (size_t)bh * Tc * HDc;
    const __half* gk = g_kh + (size_t)bh * Tc * HDc;
    const __half* gv = g_vh + (size_t)bh * Tc * HDc;

    const int r0 = qb + w * 16 + g;

    const __half2 scl = __float2half2_rn(0.125f);
    const __half2* q0p = (const __half2*)(gq + (size_t)r0 * HDc);
    const __half2* q1p = (const __half2*)(gq + (size_t)(r0 + 8) * HDc);
    uint32_t aq[4][4];
#pragma unroll
    for (int kk = 0; kk < 4; kk++) {
        aq[kk][0] = h2u(__hmul2(q0p[8 * kk + c],     scl));
        aq[kk][1] = h2u(__hmul2(q1p[8 * kk + c],     scl));
        aq[kk][2] = h2u(__hmul2(q0p[8 * kk + c + 4], scl));
        aq[kk][3] = h2u(__hmul2(q1p[8 * kk + c + 4], scl));
    }

    float o[8][4];
#pragma unroll
    for (int nt = 0; nt < 8; nt++)
#pragma unroll
        for (int j = 0; j < 4; j++) o[nt][j] = 0.f;
    float m0 = -1e30f, m1 = -1e30f, l0 = 0.f, l1 = 0.f;

    auto load_kv = [&](int t, int buf) {
        const __half* ksrc = gk + (size_t)t * KTile * HDc;
        const __half* vsrc = gv + (size_t)t * KTile * HDc;
        __half* kd = KsBase + buf * KTile * KVSH;
        __half* vd = VsBase + buf * KTile * KVSH;
#pragma unroll
        for (int i = 0; i < 2; i++) {
            int id = tid + i * 256;
            int row = id >> 3, ch = (id & 7) * 8;
            cp16(smem_u32(kd + row * KVSH + ch), ksrc + row * HDc + ch);
            cp16(smem_u32(vd + row * KVSH + ch), vsrc + row * HDc + ch);
        }
    };

    const int NT = 2 * (qt + 1);
    load_kv(0, 0); cp_commit();

    for (int t = 0; t < NT; t++) {
        const int buf = t & 1;
        if (t + 1 < NT) { load_kv(t + 1, buf ^ 1); cp_commit(); cp_wait<1>(); }
        else            { cp_wait<0>(); }
        __syncthreads();

        const uint32_t ksb = smem_u32(KsBase + buf * KTile * KVSH);
        const uint32_t vsb = smem_u32(VsBase + buf * KTile * KVSH);
        const int kb = t * KTile;

        float s[8][4];
#pragma unroll
        for (int nt = 0; nt < 8; nt++)
#pragma unroll
            for (int j = 0; j < 4; j++) s[nt][j] = 0.f;

#pragma unroll
        for (int nt = 0; nt < 8; nt++) {
            uint32_t k0r, k1r, k2r, k3r;
            uint32_t addr = ksb + (uint32_t)(((nt * 8 + (lane & 7)) * KVSH + (lane >> 3) * 8) * 2);
            ldm_x4(k0r, k1r, k2r, k3r, addr);
            mma_f16(s[nt][0], s[nt][1], s[nt][2], s[nt][3],
                    aq[0][0], aq[0][1], aq[0][2], aq[0][3], k0r, k1r);
            mma_f16(s[nt][0], s[nt][1], s[nt][2], s[nt][3],
                    aq[1][0], aq[1][1], aq[1][2], aq[1][3], k2r, k3r);
            ldm_x4(k0r, k1r, k2r, k3r, addr + 64);
            mma_f16(s[nt][0], s[nt][1], s[nt][2], s[nt][3],
                    aq[2][0], aq[2][1], aq[2][2], aq[2][3], k0r, k1r);
            mma_f16(s[nt][0], s[nt][1], s[nt][2], s[nt][3],
                    aq[3][0], aq[3][1], aq[3][2], aq[3][3], k2r, k3r);
        }

        if (kb + KTile - 1 > qb + w * 16) {
#pragma unroll
            for (int nt = 0; nt < 8; nt++) {
                int key0 = kb + nt * 8 + 2 * c;
                if (key0     > r0)     s[nt][0] = -1e30f;
                if (key0 + 1 > r0)     s[nt][1] = -1e30f;
                if (key0     > r0 + 8) s[nt][2] = -1e30f;
                if (key0 + 1 > r0 + 8) s[nt][3] = -1e30f;
            }
        }

        float rm0 = -1e30f, rm1 = -1e30f;
#pragma unroll
        for (int nt = 0; nt < 8; nt++) {
            rm0 = fmaxf(rm0, fmaxf(s[nt][0], s[nt][1]));
            rm1 = fmaxf(rm1, fmaxf(s[nt][2], s[nt][3]));
        }
        rm0 = fmaxf(rm0, __shfl_xor_sync(0xffffffffu, rm0, 1));
        rm0 = fmaxf(rm0, __shfl_xor_sync(0xffffffffu, rm0, 2));
        rm1 = fmaxf(rm1, __shfl_xor_sync(0xffffffffu, rm1, 1));
        rm1 = fmaxf(rm1, __shfl_xor_sync(0xffffffffu, rm1, 2));

        float mn0 = fmaxf(m0, rm0), mn1 = fmaxf(m1, rm1);
        float corr0 = __expf(m0 - mn0), corr1 = __expf(m1 - mn1);
        m0 = mn0; m1 = mn1;

        float ls0 = 0.f, ls1 = 0.f;
        uint32_t pu0[8], pu1[8];
#pragma unroll
        for (int nt = 0; nt < 8; nt++) {
            float p0 = __expf(s[nt][0] - m0);
            float p1 = __expf(s[nt][1] - m0);
            float p2 = __expf(s[nt][2] - m1);
            float p3 = __expf(s[nt][3] - m1);
            ls0 += p0 + p1;  ls1 += p2 + p3;
            pu0[nt] = packh(p0, p1);
            pu1[nt] = packh(p2, p3);
        }
        ls0 += __shfl_xor_sync(0xffffffffu, ls0, 1);
        ls0 += __shfl_xor_sync(0xffffffffu, ls0, 2);
        ls1 += __shfl_xor_sync(0xffffffffu, ls1, 1);
        ls1 += __shfl_xor_sync(0xffffffffu, ls1, 2);
        l0 = l0 * corr0 + ls0;
        l1 = l1 * corr1 + ls1;
#pragma unroll
        for (int nt = 0; nt < 8; nt++) {
            o[nt][0] *= corr0; o[nt][1] *= corr0;
            o[nt][2] *= corr1; o[nt][3] *= corr1;
        }

#pragma unroll
        for (int kk2 = 0; kk2 < 4; kk2++) {
            uint32_t a0 = pu0[2 * kk2],     a1 = pu1[2 * kk2];
            uint32_t a2 = pu0[2 * kk2 + 1], a3 = pu1[2 * kk2 + 1];
#pragma unroll
            for (int ntp = 0; ntp < 4; ntp++) {
                uint32_t v0, v1, v2, v3;
                uint32_t addr = vsb + (uint32_t)((
                    (kk2 * 16 + ((lane >> 3) & 1) * 8 + (lane & 7)) * KVSH +
                    (2 * ntp + (lane >> 4)) * 8) * 2);
                ldm_x4_t(v0, v1, v2, v3, addr);
                mma_f16(o[2 * ntp][0], o[2 * ntp][1], o[2 * ntp][2], o[2 * ntp][3],
                        a0, a1, a2, a3, v0, v1);
                mma_f16(o[2 * ntp + 1][0], o[2 * ntp + 1][1], o[2 * ntp + 1][2], o[2 * ntp + 1][3],
                        a0, a1, a2, a3, v2, v3);
            }
        }
        __syncthreads();
    }

    float inv0 = 1.f / l0, inv1 = 1.f / l1;
    int b = bh >> 4, h = bh & 15;
    __half* y0 = g_yh + ((size_t)b * Tc + r0) * Cc + h * HDc;
    __half* y1 = y0 + (size_t)8 * Cc;
#pragma unroll
    for (int nt = 0; nt < 8; nt++) {
        *(__half2*)&y0[nt * 8 + 2 * c] =
            __float22half2_rn(make_float2(o[nt][0] * inv0, o[nt][1] * inv0));
        *(__half2*)&y1[nt * 8 + 2 * c] =
            __float22half2_rn(make_float2(o[nt][2] * inv1, o[nt][3] * inv1));
    }
}

// ---------------------------------------------------------------------------
// Launch
// ---------------------------------------------------------------------------
extern "C" void kernel_launch(void* const* d_in, const int* in_sizes, int n_in,
                              void* d_out, int out_size)
{
    const float* x      = (const float*)d_in[0];
    const float* W_attn = (const float*)d_in[1];
    const float* b_attn = (const float*)d_in[2];
    const float* W_proj = (const float*)d_in[3];
    const float* b_proj = (const float*)d_in[4];
    float* out = (float*)d_out;

    __half *xh, *yh, *wa_t, *wp_t;
    cudaGetSymbolAddress((void**)&xh,   g_xh);
    cudaGetSymbolAddress((void**)&yh,   g_yh);
    cudaGetSymbolAddress((void**)&wa_t, g_wa_th);
    cudaGetSymbolAddress((void**)&wp_t, g_wp_th);

    static bool attr_done = false;
    if (!attr_done) {
        cudaFuncSetAttribute(gemm_h<1>, cudaFuncAttributeMaxDynamicSharedMemorySize, GEMM_SMEM);
        cudaFuncSetAttribute(gemm_h<0>, cudaFuncAttributeMaxDynamicSharedMemorySize, GEMM_SMEM);
        cudaFuncSetAttribute(attn_h, cudaFuncAttributeMaxDynamicSharedMemorySize, ATTN_SMEM);
        attr_done = true;
    }

    // Prep: x -> fp16 once; transpose+convert weights
    {
        int n4 = Bc * Tc * Cc / 4;
        conv_x_kernel<<<(n4 + 255) / 256, 256>>>(x, n4);
        transpose_conv<<<dim3(3 * Cc / 32, Cc / 32), dim3(32, 8)>>>(W_attn, wa_t, Cc, 3 * Cc);
        transpose_conv<<<dim3(Cc / 32, Cc / 32), dim3(32, 8)>>>(W_proj, wp_t, Cc, Cc);
    }
    // 1) QKV GEMM (fp16, BK=64 cp.async 3-stage + ldmatrix) -> g_qh/g_kh/g_vh
    {
        dim3 grid(3 * Cc / BNg, Bc * Tc / BMg);
        gemm_h<1><<<grid, 256, GEMM_SMEM>>>(xh, wa_t, b_attn, nullptr, Cc, 3 * Cc);
    }
    // 2) FA2 fp16 tensor-core attention -> g_yh
    {
        dim3 grid(Tc / QTile, Bc * NHc);
        attn_h<<<grid, 256, ATTN_SMEM>>>();
    }
    // 3) projection GEMM (fp16) -> out (fp32)
    {
        dim3 grid(Cc / BNg, Bc * Tc / BMg);
        gemm_h<0><<<grid, 256, GEMM_SMEM>>>(yh, wp_t, b_proj, out, Cc, Cc);
    }
}

// round 14
// speedup vs baseline: 2.1658x; 1.0045x over previous
#include <cuda_runtime.h>
#include <cuda_fp16.h>
#include <cstdint>

// Problem constants
#define Bc  4
#define Tc  2048
#define Cc  1024
#define NHc 16
#define HDc 64

// ---------------------------------------------------------------------------
// Scratch (no cudaMalloc allowed)
// ---------------------------------------------------------------------------
__device__ __half g_qh[Bc * NHc * Tc * HDc];   // [B*NH, T, HD]
__device__ __half g_kh[Bc * NHc * Tc * HDc];
__device__ __half g_vh[Bc * NHc * Tc * HDc];
__device__ __half g_yh[Bc * Tc * Cc];          // attention out [B,T,C]
__device__ __half g_xh[Bc * Tc * Cc];          // fp16 x
__device__ __half g_wa_th[3 * Cc * Cc];        // W_attn^T [3C, C]
__device__ __half g_wp_th[Cc * Cc];            // W_proj^T [C, C]

__device__ __forceinline__ uint32_t smem_u32(const void* p) {
    uint32_t a;
    asm("{ .reg .u64 t; cvta.to.shared.u64 t, %1; cvt.u32.u64 %0, t; }" : "=r"(a) : "l"(p));
    return a;
}
__device__ __forceinline__ void cp16(uint32_t dst, const void* src) {
    asm volatile("cp.async.cg.shared.global [%0], [%1], 16;" :: "r"(dst), "l"(src));
}
__device__ __forceinline__ void cp_commit() {
    asm volatile("cp.async.commit_group;" ::: "memory");
}
template <int N>
__device__ __forceinline__ void cp_wait() {
    asm volatile("cp.async.wait_group %0;" :: "n"(N) : "memory");
}
__device__ __forceinline__ uint32_t h2u(__half2 h) { return *reinterpret_cast<uint32_t*>(&h); }
__device__ __forceinline__ uint32_t packh(float a, float b) {
    return h2u(__float22half2_rn(make_float2(a, b)));
}

__device__ __forceinline__ void mma_f16(float& d0, float& d1, float& d2, float& d3,
                                        uint32_t a0, uint32_t a1, uint32_t a2, uint32_t a3,
                                        uint32_t b0, uint32_t b1)
{
    asm volatile(
        "mma.sync.aligned.m16n8k16.row.col.f32.f16.f16.f32 "
        "{%0,%1,%2,%3}, {%4,%5,%6,%7}, {%8,%9}, {%0,%1,%2,%3};"
        : "+f"(d0), "+f"(d1), "+f"(d2), "+f"(d3)
        : "r"(a0), "r"(a1), "r"(a2), "r"(a3), "r"(b0), "r"(b1));
}
__device__ __forceinline__ void ldm_x4(uint32_t& r0, uint32_t& r1, uint32_t& r2, uint32_t& r3,
                                       uint32_t addr)
{
    asm volatile("ldmatrix.sync.aligned.m8n8.x4.shared.b16 {%0,%1,%2,%3}, [%4];"
                 : "=r"(r0), "=r"(r1), "=r"(r2), "=r"(r3) : "r"(addr));
}
__device__ __forceinline__ void ldm_x4_t(uint32_t& r0, uint32_t& r1, uint32_t& r2, uint32_t& r3,
                                         uint32_t addr)
{
    asm volatile("ldmatrix.sync.aligned.m8n8.x4.trans.shared.b16 {%0,%1,%2,%3}, [%4];"
                 : "=r"(r0), "=r"(r1), "=r"(r2), "=r"(r3) : "r"(addr));
}

// ---------------------------------------------------------------------------
// fp16 mma GEMM (R13 — unchanged): Out = A@Bt^T + bias.
// BM=BN=128, BK=64, 256 threads, 64x32 warp tiles, cp.async 3-stage + ldmatrix.
// ---------------------------------------------------------------------------
constexpr int BMg = 128, BNg = 128, BKg = 64;
constexpr int GST = 72;
constexpr int STAGE_HALVES = (BMg + BNg) * GST;
constexpr int GEMM_SMEM = 3 * STAGE_HALVES * 2;         // 110592 B

template <int SCATTER>
__global__ __launch_bounds__(256, 2)
void gemm_h(const __half* __restrict__ A, const __half* __restrict__ Bt,
            const float* __restrict__ bias, float* __restrict__ Out,
            int K, int N)
{
    extern __shared__ __half sg[];

    const int tid  = threadIdx.x;
    const int lane = tid & 31;
    const int wid  = tid >> 5;
    const int g    = lane >> 2;
    const int c    = lane & 3;
    const int warp_m = (wid & 1) * 64;
    const int warp_n = (wid >> 1) * 32;
    const int lrow = lane & 15;
    const int lcol = (lane >> 4) * 8;

    const __half* Asrc0 = A  + (size_t)blockIdx.y * BMg * K;
    const __half* Bsrc0 = Bt + (size_t)blockIdx.x * BNg * K;

    auto load_stage = [&](int kt, int st) {
        __half* sA = sg + st * STAGE_HALVES;
        __half* sB = sA + BMg * GST;
        const __half* Asrc = Asrc0 + kt * BKg;
        const __half* Bsrc = Bsrc0 + kt * BKg;
#pragma unroll
        for (int i = 0; i < 4; i++) {
            int ch = tid + i * 256;
            int row = ch >> 3, q = (ch & 7) * 8;
            cp16(smem_u32(sA + row * GST + q), Asrc + (size_t)row * K + q);
            cp16(smem_u32(sB + row * GST + q), Bsrc + (size_t)row * K + q);
        }
    };

    float acc[4][4][4];
#pragma unroll
    for (int i = 0; i < 4; i++)
#pragma unroll
        for (int j = 0; j < 4; j++)
#pragma unroll
            for (int r = 0; r < 4; r++) acc[i][j][r] = 0.f;

    const int NT = K / BKg;
    load_stage(0, 0); cp_commit();
    load_stage(1, 1); cp_commit();

    int st = 0;
    for (int kt = 0; kt < NT; kt++) {
        if (kt + 1 < NT) cp_wait<1>(); else cp_wait<0>();
        __syncthreads();

        const uint32_t sAu = smem_u32(sg + st * STAGE_HALVES);
        const uint32_t sBu = sAu + BMg * GST * 2;

#pragma unroll
        for (int ks = 0; ks < 4; ks++) {
            uint32_t af[4][4], bf[4][2];
#pragma unroll
            for (int mt = 0; mt < 4; mt++) {
                uint32_t addr = sAu + (uint32_t)(((warp_m + mt * 16 + lrow) * GST
                                                 + ks * 16 + lcol) * 2);
                ldm_x4(af[mt][0], af[mt][1], af[mt][2], af[mt][3], addr);
            }
#pragma unroll
            for (int bp = 0; bp < 2; bp++) {
                uint32_t addr = sBu + (uint32_t)(((warp_n + bp * 16 + lrow) * GST
                                                 + ks * 16 + lcol) * 2);
                ldm_x4(bf[2 * bp][0], bf[2 * bp + 1][0],
                       bf[2 * bp][1], bf[2 * bp + 1][1], addr);
            }
#pragma unroll
            for (int mt = 0; mt < 4; mt++)
#pragma unroll
                for (int nt = 0; nt < 4; nt++)
                    mma_f16(acc[mt][nt][0], acc[mt][nt][1], acc[mt][nt][2], acc[mt][nt][3],
                            af[mt][0], af[mt][1], af[mt][2], af[mt][3],
                            bf[nt][0], bf[nt][1]);
        }

        if (kt + 2 < NT) {
            int s2 = st + 2; if (s2 >= 3) s2 -= 3;
            load_stage(kt + 2, s2);
            cp_commit();
        }
        if (++st == 3) st = 0;
    }

#pragma unroll
    for (int mt = 0; mt < 4; mt++) {
#pragma unroll
        for (int nt = 0; nt < 4; nt++) {
            int n0 = blockIdx.x * BNg + warp_n + nt * 8 + 2 * c;
            float2 bb = *(const float2*)(bias + n0);
            int m0 = blockIdx.y * BMg + warp_m + mt * 16 + g;
#pragma unroll
            for (int rh = 0; rh < 2; rh++) {
                int m = m0 + rh * 8;
                float vx = acc[mt][nt][2 * rh + 0] + bb.x;
                float vy = acc[mt][nt][2 * rh + 1] + bb.y;
                if (SCATTER) {
                    __half2 hv = __float22half2_rn(make_float2(vx, vy));
                    int which = n0 >> 10, c0 = n0 & 1023;
                    int h = c0 >> 6, d = c0 & 63;
                    int b = m >> 11, t = m & 2047;
                    __half* dst = (which == 0) ? g_qh : ((which == 1) ? g_kh : g_vh);
                    *(__half2*)&dst[(((size_t)(b * NHc + h)) * Tc + t) * HDc + d] = hv;
                } else {
                    *(float2*)&Out[(size_t)m * N + n0] = make_float2(vx, vy);
                }
            }
        }
    }
}

// ---------------------------------------------------------------------------
// Prep kernels
// ---------------------------------------------------------------------------
__global__ void conv_x_kernel(const float* __restrict__ x, int n4)
{
    int i = blockIdx.x * blockDim.x + threadIdx.x;
    if (i < n4) {
        float4 v = ((const float4*)x)[i];
        ((__half2*)g_xh)[2 * i]     = __float22half2_rn(make_float2(v.x, v.y));
        ((__half2*)g_xh)[2 * i + 1] = __float22half2_rn(make_float2(v.z, v.w));
    }
}

__global__ void transpose_conv(const float* __restrict__ W, __half* __restrict__ Bt,
                               int K, int N)
{
    __shared__ float t[32][33];
    int n0 = blockIdx.x * 32, k0 = blockIdx.y * 32;
    int tx = threadIdx.x, ty = threadIdx.y;
#pragma unroll
    for (int i = 0; i < 32; i += 8)
        t[ty + i][tx] = W[(size_t)(k0 + ty + i) * N + n0 + tx];
    __syncthreads();
#pragma unroll
    for (int i = 0; i < 32; i += 8)
        Bt[(size_t)(n0 + ty + i) * K + k0 + tx] = __float2half_rn(t[tx][ty + i]);
}

// ---------------------------------------------------------------------------
// FA2 attention, fp16 mma. NEW: 128-key double-buffered stages processed as
// two 64-key chunks (half the barriers) + per-warp skip of fully-masked
// diagonal chunks. Register footprint unchanged (s[8][4] reused per chunk).
// ---------------------------------------------------------------------------
constexpr int QTile = 128;
constexpr int KStage = 128;                              // keys per smem stage
constexpr int KVSH  = 72;
constexpr int ATTN_SMEM = 2 * 2 * KStage * KVSH * 2;     // 73728 B

__global__ __launch_bounds__(256, 2)
void attn_h()
{
    extern __shared__ __half smh[];
    __half* KsBase = smh;                                // [2][128][72]
    __half* VsBase = smh + 2 * KStage * KVSH;            // [2][128][72]

    const int qt  = (gridDim.x - 1) - blockIdx.x;        // heavy tiles first
    const int bh  = blockIdx.y;
    const int qb  = qt * QTile;
    const int tid = threadIdx.x;
    const int lane = tid & 31;
    const int w   = tid >> 5;
    const int g   = lane >> 2;
    const int c   = lane & 3;

    const __half* gq = g_qh + (size_t)bh * Tc * HDc;
    const __half* gk = g_kh + (size_t)bh * Tc * HDc;
    const __half* gv = g_vh + (size_t)bh * Tc * HDc;

    const int r0 = qb + w * 16 + g;                      // rows r0, r0+8
    const int wlast = qb + w * 16 + 15;                  // warp's last q row

    const __half2 scl = __float2half2_rn(0.125f);
    const __half2* q0p = (const __half2*)(gq + (size_t)r0 * HDc);
    const __half2* q1p = (const __half2*)(gq + (size_t)(r0 + 8) * HDc);
    uint32_t aq[4][4];
#pragma unroll
    for (int kk = 0; kk < 4; kk++) {
        aq[kk][0] = h2u(__hmul2(q0p[8 * kk + c],     scl));
        aq[kk][1] = h2u(__hmul2(q1p[8 * kk + c],     scl));
        aq[kk][2] = h2u(__hmul2(q0p[8 * kk + c + 4], scl));
        aq[kk][3] = h2u(__hmul2(q1p[8 * kk + c + 4], scl));
    }

    float o[8][4];
#pragma unroll
    for (int nt = 0; nt < 8; nt++)
#pragma unroll
        for (int j = 0; j < 4; j++) o[nt][j] = 0.f;
    float m0 = -1e30f, m1 = -1e30f, l0 = 0.f, l1 = 0.f;

    auto load_kv = [&](int t, int buf) {
        const __half* ksrc = gk + (size_t)t * KStage * HDc;
        const __half* vsrc = gv + (size_t)t * KStage * HDc;
        __half* kd = KsBase + buf * KStage * KVSH;
        __half* vd = VsBase + buf * KStage * KVSH;
#pragma unroll
        for (int i = 0; i < 4; i++) {
            int id = tid + i * 256;                      // 0..1023
            int row = id >> 3, ch = (id & 7) * 8;
            cp16(smem_u32(kd + row * KVSH + ch), ksrc + row * HDc + ch);
            cp16(smem_u32(vd + row * KVSH + ch), vsrc + row * HDc + ch);
        }
    };

    const int NT = qt + 1;                               // 128-key stages
    load_kv(0, 0); cp_commit();

    for (int t = 0; t < NT; t++) {
        const int buf = t & 1;
        if (t + 1 < NT) { load_kv(t + 1, buf ^ 1); cp_commit(); cp_wait<1>(); }
        else            { cp_wait<0>(); }
        __syncthreads();

        const uint32_t ksb0 = smem_u32(KsBase + buf * KStage * KVSH);
        const uint32_t vsb0 = smem_u32(VsBase + buf * KStage * KVSH);

#pragma unroll
        for (int ch2 = 0; ch2 < 2; ch2++) {
            const int kb = t * KStage + ch2 * 64;
            if (kb > wlast) continue;                    // fully-masked chunk: skip
            const uint32_t ksb = ksb0 + (uint32_t)(ch2 * 64 * KVSH * 2);
            const uint32_t vsb = vsb0 + (uint32_t)(ch2 * 64 * KVSH * 2);

            // ---- S = Q @ K^T ----
            float s[8][4];
#pragma unroll
            for (int nt = 0; nt < 8; nt++)
#pragma unroll
                for (int j = 0; j < 4; j++) s[nt][j] = 0.f;

#pragma unroll
            for (int nt = 0; nt < 8; nt++) {
                uint32_t k0r, k1r, k2r, k3r;
                uint32_t addr = ksb + (uint32_t)(((nt * 8 + (lane & 7)) * KVSH
                                                 + (lane >> 3) * 8) * 2);
                ldm_x4(k0r, k1r, k2r, k3r, addr);
                mma_f16(s[nt][0], s[nt][1], s[nt][2], s[nt][3],
                        aq[0][0], aq[0][1], aq[0][2], aq[0][3], k0r, k1r);
                mma_f16(s[nt][0], s[nt][1], s[nt][2], s[nt][3],
                        aq[1][0], aq[1][1], aq[1][2], aq[1][3], k2r, k3r);
                ldm_x4(k0r, k1r, k2r, k3r, addr + 64);
                mma_f16(s[nt][0], s[nt][1], s[nt][2], s[nt][3],
                        aq[2][0], aq[2][1], aq[2][2], aq[2][3], k0r, k1r);
                mma_f16(s[nt][0], s[nt][1], s[nt][2], s[nt][3],
                        aq[3][0], aq[3][1], aq[3][2], aq[3][3], k2r, k3r);
            }

            // ---- causal mask (chunks crossing this warp's diagonal) ----
            if (kb + 63 > qb + w * 16) {
#pragma unroll
                for (int nt = 0; nt < 8; nt++) {
                    int key0 = kb + nt * 8 + 2 * c;
                    if (key0     > r0)     s[nt][0] = -1e30f;
                    if (key0 + 1 > r0)     s[nt][1] = -1e30f;
                    if (key0     > r0 + 8) s[nt][2] = -1e30f;
                    if (key0 + 1 > r0 + 8) s[nt][3] = -1e30f;
                }
            }

            // ---- online softmax ----
            float rm0 = -1e30f, rm1 = -1e30f;
#pragma unroll
            for (int nt = 0; nt < 8; nt++) {
                rm0 = fmaxf(rm0, fmaxf(s[nt][0], s[nt][1]));
                rm1 = fmaxf(rm1, fmaxf(s[nt][2], s[nt][3]));
            }
            rm0 = fmaxf(rm0, __shfl_xor_sync(0xffffffffu, rm0, 1));
            rm0 = fmaxf(rm0, __shfl_xor_sync(0xffffffffu, rm0, 2));
            rm1 = fmaxf(rm1, __shfl_xor_sync(0xffffffffu, rm1, 1));
            rm1 = fmaxf(rm1, __shfl_xor_sync(0xffffffffu, rm1, 2));

            float mn0 = fmaxf(m0, rm0), mn1 = fmaxf(m1, rm1);
            float corr0 = __expf(m0 - mn0), corr1 = __expf(m1 - mn1);
            m0 = mn0; m1 = mn1;

            float ls0 = 0.f, ls1 = 0.f;
            uint32_t pu0[8], pu1[8];
#pragma unroll
            for (int nt = 0; nt < 8; nt++) {
                float p0 = __expf(s[nt][0] - m0);
                float p1 = __expf(s[nt][1] - m0);
                float p2 = __expf(s[nt][2] - m1);
                float p3 = __expf(s[nt][3] - m1);
                ls0 += p0 + p1;  ls1 += p2 + p3;
                pu0[nt] = packh(p0, p1);
                pu1[nt] = packh(p2, p3);
            }
            ls0 += __shfl_xor_sync(0xffffffffu, ls0, 1);
            ls0 += __shfl_xor_sync(0xffffffffu, ls0, 2);
            ls1 += __shfl_xor_sync(0xffffffffu, ls1, 1);
            ls1 += __shfl_xor_sync(0xffffffffu, ls1, 2);
            l0 = l0 * corr0 + ls0;
            l1 = l1 * corr1 + ls1;
#pragma unroll
            for (int nt = 0; nt < 8; nt++) {
                o[nt][0] *= corr0; o[nt][1] *= corr0;
                o[nt][2] *= corr1; o[nt][3] *= corr1;
            }

            // ---- O += P @ V ----
#pragma unroll
            for (int kk2 = 0; kk2 < 4; kk2++) {
                uint32_t a0 = pu0[2 * kk2],     a1 = pu1[2 * kk2];
                uint32_t a2 = pu0[2 * kk2 + 1], a3 = pu1[2 * kk2 + 1];
#pragma unroll
                for (int ntp = 0; ntp < 4; ntp++) {
                    uint32_t v0, v1, v2, v3;
                    uint32_t addr = vsb + (uint32_t)((
                        (kk2 * 16 + ((lane >> 3) & 1) * 8 + (lane & 7)) * KVSH +
                        (2 * ntp + (lane >> 4)) * 8) * 2);
                    ldm_x4_t(v0, v1, v2, v3, addr);
                    mma_f16(o[2 * ntp][0], o[2 * ntp][1], o[2 * ntp][2], o[2 * ntp][3],
                            a0, a1, a2, a3, v0, v1);
                    mma_f16(o[2 * ntp + 1][0], o[2 * ntp + 1][1],
                            o[2 * ntp + 1][2], o[2 * ntp + 1][3],
                            a0, a1, a2, a3, v2, v3);
                }
            }
        }
        __syncthreads();
    }

    float inv0 = 1.f / l0, inv1 = 1.f / l1;
    int b = bh >> 4, h = bh & 15;
    __half* y0 = g_yh + ((size_t)b * Tc + r0) * Cc + h * HDc;
    __half* y1 = y0 + (size_t)8 * Cc;
#pragma unroll
    for (int nt = 0; nt < 8; nt++) {
        *(__half2*)&y0[nt * 8 + 2 * c] =
            __float22half2_rn(make_float2(o[nt][0] * inv0, o[nt][1] * inv0));
        *(__half2*)&y1[nt * 8 + 2 * c] =
            __float22half2_rn(make_float2(o[nt][2] * inv1, o[nt][3] * inv1));
    }
}

// ---------------------------------------------------------------------------
// Launch
// ---------------------------------------------------------------------------
extern "C" void kernel_launch(void* const* d_in, const int* in_sizes, int n_in,
                              void* d_out, int out_size)
{
    const float* x      = (const float*)d_in[0];
    const float* W_attn = (const float*)d_in[1];
    const float* b_attn = (const float*)d_in[2];
    const float* W_proj = (const float*)d_in[3];
    const float* b_proj = (const float*)d_in[4];
    float* out = (float*)d_out;

    __half *xh, *yh, *wa_t, *wp_t;
    cudaGetSymbolAddress((void**)&xh,   g_xh);
    cudaGetSymbolAddress((void**)&yh,   g_yh);
    cudaGetSymbolAddress((void**)&wa_t, g_wa_th);
    cudaGetSymbolAddress((void**)&wp_t, g_wp_th);

    static bool attr_done = false;
    if (!attr_done) {
        cudaFuncSetAttribute(gemm_h<1>, cudaFuncAttributeMaxDynamicSharedMemorySize, GEMM_SMEM);
        cudaFuncSetAttribute(gemm_h<0>, cudaFuncAttributeMaxDynamicSharedMemorySize, GEMM_SMEM);
        cudaFuncSetAttribute(attn_h, cudaFuncAttributeMaxDynamicSharedMemorySize, ATTN_SMEM);
        attr_done = true;
    }

    // Prep: x -> fp16; transpose+convert weights
    {
        int n4 = Bc * Tc * Cc / 4;
        conv_x_kernel<<<(n4 + 255) / 256, 256>>>(x, n4);
        transpose_conv<<<dim3(3 * Cc / 32, Cc / 32), dim3(32, 8)>>>(W_attn, wa_t, Cc, 3 * Cc);
        transpose_conv<<<dim3(Cc / 32, Cc / 32), dim3(32, 8)>>>(W_proj, wp_t, Cc, Cc);
    }
    // 1) QKV GEMM -> g_qh/g_kh/g_vh
    {
        dim3 grid(3 * Cc / BNg, Bc * Tc / BMg);
        gemm_h<1><<<grid, 256, GEMM_SMEM>>>(xh, wa_t, b_attn, nullptr, Cc, 3 * Cc);
    }
    // 2) FA2 attention (128-key stages, chunked) -> g_yh
    {
        dim3 grid(Tc / QTile, Bc * NHc);
        attn_h<<<grid, 256, ATTN_SMEM>>>();
    }
    // 3) projection GEMM -> out
    {
        dim3 grid(Cc / BNg, Bc * Tc / BMg);
        gemm_h<0><<<grid, 256, GEMM_SMEM>>>(yh, wp_t, b_proj, out, Cc, Cc);
    }
}

// round 15
// speedup vs baseline: 2.2142x; 1.0223x over previous
#include <cuda_runtime.h>
#include <cuda_fp16.h>
#include <cstdint>

// Problem constants
#define Bc  4
#define Tc  2048
#define Cc  1024
#define NHc 16
#define HDc 64

// ---------------------------------------------------------------------------
// Scratch (no cudaMalloc allowed)
// ---------------------------------------------------------------------------
__device__ __half g_qh[Bc * NHc * Tc * HDc];   // [B*NH, T, HD]
__device__ __half g_kh[Bc * NHc * Tc * HDc];
__device__ __half g_vh[Bc * NHc * Tc * HDc];
__device__ __half g_yh[Bc * Tc * Cc];          // attention out [B,T,C]
__device__ __half g_xh[Bc * Tc * Cc];          // fp16 x
__device__ __half g_wa_th[3 * Cc * Cc];        // W_attn^T [3C, C]
__device__ __half g_wp_th[Cc * Cc];            // W_proj^T [C, C]

__device__ __forceinline__ uint32_t smem_u32(const void* p) {
    uint32_t a;
    asm("{ .reg .u64 t; cvta.to.shared.u64 t, %1; cvt.u32.u64 %0, t; }" : "=r"(a) : "l"(p));
    return a;
}
__device__ __forceinline__ void cp16(uint32_t dst, const void* src) {
    asm volatile("cp.async.cg.shared.global [%0], [%1], 16;" :: "r"(dst), "l"(src));
}
__device__ __forceinline__ void cp_commit() {
    asm volatile("cp.async.commit_group;" ::: "memory");
}
template <int N>
__device__ __forceinline__ void cp_wait() {
    asm volatile("cp.async.wait_group %0;" :: "n"(N) : "memory");
}
__device__ __forceinline__ uint32_t h2u(__half2 h) { return *reinterpret_cast<uint32_t*>(&h); }
__device__ __forceinline__ uint32_t packh(float a, float b) {
    return h2u(__float22half2_rn(make_float2(a, b)));
}

__device__ __forceinline__ void mma_f16(float& d0, float& d1, float& d2, float& d3,
                                        uint32_t a0, uint32_t a1, uint32_t a2, uint32_t a3,
                                        uint32_t b0, uint32_t b1)
{
    asm volatile(
        "mma.sync.aligned.m16n8k16.row.col.f32.f16.f16.f32 "
        "{%0,%1,%2,%3}, {%4,%5,%6,%7}, {%8,%9}, {%0,%1,%2,%3};"
        : "+f"(d0), "+f"(d1), "+f"(d2), "+f"(d3)
        : "r"(a0), "r"(a1), "r"(a2), "r"(a3), "r"(b0), "r"(b1));
}
__device__ __forceinline__ void ldm_x4(uint32_t& r0, uint32_t& r1, uint32_t& r2, uint32_t& r3,
                                       uint32_t addr)
{
    asm volatile("ldmatrix.sync.aligned.m8n8.x4.shared.b16 {%0,%1,%2,%3}, [%4];"
                 : "=r"(r0), "=r"(r1), "=r"(r2), "=r"(r3) : "r"(addr));
}
__device__ __forceinline__ void ldm_x4_t(uint32_t& r0, uint32_t& r1, uint32_t& r2, uint32_t& r3,
                                         uint32_t addr)
{
    asm volatile("ldmatrix.sync.aligned.m8n8.x4.trans.shared.b16 {%0,%1,%2,%3}, [%4];"
                 : "=r"(r0), "=r"(r1), "=r"(r2), "=r"(r3) : "r"(addr));
}

// ---------------------------------------------------------------------------
// fp16 mma GEMM (R13 — unchanged): Out = A@Bt^T + bias.
// BM=BN=128, BK=64, 256 threads, 64x32 warp tiles, cp.async 3-stage + ldmatrix.
// ---------------------------------------------------------------------------
constexpr int BMg = 128, BNg = 128, BKg = 64;
constexpr int GST = 72;
constexpr int STAGE_HALVES = (BMg + BNg) * GST;
constexpr int GEMM_SMEM = 3 * STAGE_HALVES * 2;         // 110592 B

template <int SCATTER>
__global__ __launch_bounds__(256, 2)
void gemm_h(const __half* __restrict__ A, const __half* __restrict__ Bt,
            const float* __restrict__ bias, float* __restrict__ Out,
            int K, int N)
{
    extern __shared__ __half sg[];

    const int tid  = threadIdx.x;
    const int lane = tid & 31;
    const int wid  = tid >> 5;
    const int g    = lane >> 2;
    const int c    = lane & 3;
    const int warp_m = (wid & 1) * 64;
    const int warp_n = (wid >> 1) * 32;
    const int lrow = lane & 15;
    const int lcol = (lane >> 4) * 8;

    const __half* Asrc0 = A  + (size_t)blockIdx.y * BMg * K;
    const __half* Bsrc0 = Bt + (size_t)blockIdx.x * BNg * K;

    auto load_stage = [&](int kt, int st) {
        __half* sA = sg + st * STAGE_HALVES;
        __half* sB = sA + BMg * GST;
        const __half* Asrc = Asrc0 + kt * BKg;
        const __half* Bsrc = Bsrc0 + kt * BKg;
#pragma unroll
        for (int i = 0; i < 4; i++) {
            int ch = tid + i * 256;
            int row = ch >> 3, q = (ch & 7) * 8;
            cp16(smem_u32(sA + row * GST + q), Asrc + (size_t)row * K + q);
            cp16(smem_u32(sB + row * GST + q), Bsrc + (size_t)row * K + q);
        }
    };

    float acc[4][4][4];
#pragma unroll
    for (int i = 0; i < 4; i++)
#pragma unroll
        for (int j = 0; j < 4; j++)
#pragma unroll
            for (int r = 0; r < 4; r++) acc[i][j][r] = 0.f;

    const int NT = K / BKg;
    load_stage(0, 0); cp_commit();
    load_stage(1, 1); cp_commit();

    int st = 0;
    for (int kt = 0; kt < NT; kt++) {
        if (kt + 1 < NT) cp_wait<1>(); else cp_wait<0>();
        __syncthreads();

        const uint32_t sAu = smem_u32(sg + st * STAGE_HALVES);
        const uint32_t sBu = sAu + BMg * GST * 2;

#pragma unroll
        for (int ks = 0; ks < 4; ks++) {
            uint32_t af[4][4], bf[4][2];
#pragma unroll
            for (int mt = 0; mt < 4; mt++) {
                uint32_t addr = sAu + (uint32_t)(((warp_m + mt * 16 + lrow) * GST
                                                 + ks * 16 + lcol) * 2);
                ldm_x4(af[mt][0], af[mt][1], af[mt][2], af[mt][3], addr);
            }
#pragma unroll
            for (int bp = 0; bp < 2; bp++) {
                uint32_t addr = sBu + (uint32_t)(((warp_n + bp * 16 + lrow) * GST
                                                 + ks * 16 + lcol) * 2);
                ldm_x4(bf[2 * bp][0], bf[2 * bp + 1][0],
                       bf[2 * bp][1], bf[2 * bp + 1][1], addr);
            }
#pragma unroll
            for (int mt = 0; mt < 4; mt++)
#pragma unroll
                for (int nt = 0; nt < 4; nt++)
                    mma_f16(acc[mt][nt][0], acc[mt][nt][1], acc[mt][nt][2], acc[mt][nt][3],
                            af[mt][0], af[mt][1], af[mt][2], af[mt][3],
                            bf[nt][0], bf[nt][1]);
        }

        if (kt + 2 < NT) {
            int s2 = st + 2; if (s2 >= 3) s2 -= 3;
            load_stage(kt + 2, s2);
            cp_commit();
        }
        if (++st == 3) st = 0;
    }

#pragma unroll
    for (int mt = 0; mt < 4; mt++) {
#pragma unroll
        for (int nt = 0; nt < 4; nt++) {
            int n0 = blockIdx.x * BNg + warp_n + nt * 8 + 2 * c;
            float2 bb = *(const float2*)(bias + n0);
            int m0 = blockIdx.y * BMg + warp_m + mt * 16 + g;
#pragma unroll
            for (int rh = 0; rh < 2; rh++) {
                int m = m0 + rh * 8;
                float vx = acc[mt][nt][2 * rh + 0] + bb.x;
                float vy = acc[mt][nt][2 * rh + 1] + bb.y;
                if (SCATTER) {
                    __half2 hv = __float22half2_rn(make_float2(vx, vy));
                    int which = n0 >> 10, c0 = n0 & 1023;
                    int h = c0 >> 6, d = c0 & 63;
                    int b = m >> 11, t = m & 2047;
                    __half* dst = (which == 0) ? g_qh : ((which == 1) ? g_kh : g_vh);
                    *(__half2*)&dst[(((size_t)(b * NHc + h)) * Tc + t) * HDc + d] = hv;
                } else {
                    *(float2*)&Out[(size_t)m * N + n0] = make_float2(vx, vy);
                }
            }
        }
    }
}

// ---------------------------------------------------------------------------
// Prep kernels
// ---------------------------------------------------------------------------
__global__ void conv_x_kernel(const float* __restrict__ x, int n4)
{
    int i = blockIdx.x * blockDim.x + threadIdx.x;
    if (i < n4) {
        float4 v = ((const float4*)x)[i];
        ((__half2*)g_xh)[2 * i]     = __float22half2_rn(make_float2(v.x, v.y));
        ((__half2*)g_xh)[2 * i + 1] = __float22half2_rn(make_float2(v.z, v.w));
    }
}

__global__ void transpose_conv(const float* __restrict__ W, __half* __restrict__ Bt,
                               int K, int N)
{
    __shared__ float t[32][33];
    int n0 = blockIdx.x * 32, k0 = blockIdx.y * 32;
    int tx = threadIdx.x, ty = threadIdx.y;
#pragma unroll
    for (int i = 0; i < 32; i += 8)
        t[ty + i][tx] = W[(size_t)(k0 + ty + i) * N + n0 + tx];
    __syncthreads();
#pragma unroll
    for (int i = 0; i < 32; i += 8)
        Bt[(size_t)(n0 + ty + i) * K + k0 + tx] = __float2half_rn(t[tx][ty + i]);
}

// ---------------------------------------------------------------------------
// FA2 attention, fp16 mma. NEW: paired q-tiles for uniform load balance.
// grid.x = 8; block bx processes q-tiles (15-bx) then (bx):
// total work = (16-bx)+(bx+1) = 17 stages for EVERY block.
// 128-key double-buffered stages, two 64-key chunks, per-warp masked-chunk skip.
// ---------------------------------------------------------------------------
constexpr int QTile = 128;
constexpr int NQT   = Tc / QTile;                        // 16
constexpr int KStage = 128;
constexpr int KVSH  = 72;
constexpr int ATTN_SMEM = 2 * 2 * KStage * KVSH * 2;     // 73728 B

__global__ __launch_bounds__(256, 2)
void attn_h()
{
    extern __shared__ __half smh[];
    __half* KsBase = smh;                                // [2][128][72]
    __half* VsBase = smh + 2 * KStage * KVSH;            // [2][128][72]

    const int bh  = blockIdx.y;
    const int tid = threadIdx.x;
    const int lane = tid & 31;
    const int w   = tid >> 5;
    const int g   = lane >> 2;
    const int c   = lane & 3;

    const __half* gq = g_qh + (size_t)bh * Tc * HDc;
    const __half* gk = g_kh + (size_t)bh * Tc * HDc;
    const __half* gv = g_vh + (size_t)bh * Tc * HDc;

    const __half2 scl = __float2half2_rn(0.125f);

    auto load_kv = [&](int t, int buf) {
        const __half* ksrc = gk + (size_t)t * KStage * HDc;
        const __half* vsrc = gv + (size_t)t * KStage * HDc;
        __half* kd = KsBase + buf * KStage * KVSH;
        __half* vd = VsBase + buf * KStage * KVSH;
#pragma unroll
        for (int i = 0; i < 4; i++) {
            int id = tid + i * 256;                      // 0..1023
            int row = id >> 3, ch = (id & 7) * 8;
            cp16(smem_u32(kd + row * KVSH + ch), ksrc + row * HDc + ch);
            cp16(smem_u32(vd + row * KVSH + ch), vsrc + row * HDc + ch);
        }
    };

#pragma unroll 1
    for (int pass = 0; pass < 2; pass++) {
        const int qt = (pass == 0) ? (NQT - 1 - blockIdx.x) : blockIdx.x;
        const int qb = qt * QTile;
        const int r0 = qb + w * 16 + g;                  // rows r0, r0+8
        const int wlast = qb + w * 16 + 15;

        // Q fragments for this tile (pre-scaled)
        const __half2* q0p = (const __half2*)(gq + (size_t)r0 * HDc);
        const __half2* q1p = (const __half2*)(gq + (size_t)(r0 + 8) * HDc);
        uint32_t aq[4][4];
#pragma unroll
        for (int kk = 0; kk < 4; kk++) {
            aq[kk][0] = h2u(__hmul2(q0p[8 * kk + c],     scl));
            aq[kk][1] = h2u(__hmul2(q1p[8 * kk + c],     scl));
            aq[kk][2] = h2u(__hmul2(q0p[8 * kk + c + 4], scl));
            aq[kk][3] = h2u(__hmul2(q1p[8 * kk + c + 4], scl));
        }

        float o[8][4];
#pragma unroll
        for (int nt = 0; nt < 8; nt++)
#pragma unroll
            for (int j = 0; j < 4; j++) o[nt][j] = 0.f;
        float m0 = -1e30f, m1 = -1e30f, l0 = 0.f, l1 = 0.f;

        const int NT = qt + 1;                           // 128-key stages
        load_kv(0, 0); cp_commit();

        for (int t = 0; t < NT; t++) {
            const int buf = t & 1;
            if (t + 1 < NT) { load_kv(t + 1, buf ^ 1); cp_commit(); cp_wait<1>(); }
            else            { cp_wait<0>(); }
            __syncthreads();

            const uint32_t ksb0 = smem_u32(KsBase + buf * KStage * KVSH);
            const uint32_t vsb0 = smem_u32(VsBase + buf * KStage * KVSH);

#pragma unroll
            for (int ch2 = 0; ch2 < 2; ch2++) {
                const int kb = t * KStage + ch2 * 64;
                if (kb > wlast) continue;                // fully-masked chunk
                const uint32_t ksb = ksb0 + (uint32_t)(ch2 * 64 * KVSH * 2);
                const uint32_t vsb = vsb0 + (uint32_t)(ch2 * 64 * KVSH * 2);

                // ---- S = Q @ K^T ----
                float s[8][4];
#pragma unroll
                for (int nt = 0; nt < 8; nt++)
#pragma unroll
                    for (int j = 0; j < 4; j++) s[nt][j] = 0.f;

#pragma unroll
                for (int nt = 0; nt < 8; nt++) {
                    uint32_t k0r, k1r, k2r, k3r;
                    uint32_t addr = ksb + (uint32_t)(((nt * 8 + (lane & 7)) * KVSH
                                                     + (lane >> 3) * 8) * 2);
                    ldm_x4(k0r, k1r, k2r, k3r, addr);
                    mma_f16(s[nt][0], s[nt][1], s[nt][2], s[nt][3],
                            aq[0][0], aq[0][1], aq[0][2], aq[0][3], k0r, k1r);
                    mma_f16(s[nt][0], s[nt][1], s[nt][2], s[nt][3],
                            aq[1][0], aq[1][1], aq[1][2], aq[1][3], k2r, k3r);
                    ldm_x4(k0r, k1r, k2r, k3r, addr + 64);
                    mma_f16(s[nt][0], s[nt][1], s[nt][2], s[nt][3],
                            aq[2][0], aq[2][1], aq[2][2], aq[2][3], k0r, k1r);
                    mma_f16(s[nt][0], s[nt][1], s[nt][2], s[nt][3],
                            aq[3][0], aq[3][1], aq[3][2], aq[3][3], k2r, k3r);
                }

                // ---- causal mask ----
                if (kb + 63 > qb + w * 16) {
#pragma unroll
                    for (int nt = 0; nt < 8; nt++) {
                        int key0 = kb + nt * 8 + 2 * c;
                        if (key0     > r0)     s[nt][0] = -1e30f;
                        if (key0 + 1 > r0)     s[nt][1] = -1e30f;
                        if (key0     > r0 + 8) s[nt][2] = -1e30f;
                        if (key0 + 1 > r0 + 8) s[nt][3] = -1e30f;
                    }
                }

                // ---- online softmax ----
                float rm0 = -1e30f, rm1 = -1e30f;
#pragma unroll
                for (int nt = 0; nt < 8; nt++) {
                    rm0 = fmaxf(rm0, fmaxf(s[nt][0], s[nt][1]));
                    rm1 = fmaxf(rm1, fmaxf(s[nt][2], s[nt][3]));
                }
                rm0 = fmaxf(rm0, __shfl_xor_sync(0xffffffffu, rm0, 1));
                rm0 = fmaxf(rm0, __shfl_xor_sync(0xffffffffu, rm0, 2));
                rm1 = fmaxf(rm1, __shfl_xor_sync(0xffffffffu, rm1, 1));
                rm1 = fmaxf(rm1, __shfl_xor_sync(0xffffffffu, rm1, 2));

                float mn0 = fmaxf(m0, rm0), mn1 = fmaxf(m1, rm1);
                float corr0 = __expf(m0 - mn0), corr1 = __expf(m1 - mn1);
                m0 = mn0; m1 = mn1;

                float ls0 = 0.f, ls1 = 0.f;
                uint32_t pu0[8], pu1[8];
#pragma unroll
                for (int nt = 0; nt < 8; nt++) {
                    float p0 = __expf(s[nt][0] - m0);
                    float p1 = __expf(s[nt][1] - m0);
                    float p2 = __expf(s[nt][2] - m1);
                    float p3 = __expf(s[nt][3] - m1);
                    ls0 += p0 + p1;  ls1 += p2 + p3;
                    pu0[nt] = packh(p0, p1);
                    pu1[nt] = packh(p2, p3);
                }
                ls0 += __shfl_xor_sync(0xffffffffu, ls0, 1);
                ls0 += __shfl_xor_sync(0xffffffffu, ls0, 2);
                ls1 += __shfl_xor_sync(0xffffffffu, ls1, 1);
                ls1 += __shfl_xor_sync(0xffffffffu, ls1, 2);
                l0 = l0 * corr0 + ls0;
                l1 = l1 * corr1 + ls1;
#pragma unroll
                for (int nt = 0; nt < 8; nt++) {
                    o[nt][0] *= corr0; o[nt][1] *= corr0;
                    o[nt][2] *= corr1; o[nt][3] *= corr1;
                }

                // ---- O += P @ V ----
#pragma unroll
                for (int kk2 = 0; kk2 < 4; kk2++) {
                    uint32_t a0 = pu0[2 * kk2],     a1 = pu1[2 * kk2];
                    uint32_t a2 = pu0[2 * kk2 + 1], a3 = pu1[2 * kk2 + 1];
#pragma unroll
                    for (int ntp = 0; ntp < 4; ntp++) {
                        uint32_t v0, v1, v2, v3;
                        uint32_t addr = vsb + (uint32_t)((
                            (kk2 * 16 + ((lane >> 3) & 1) * 8 + (lane & 7)) * KVSH +
                            (2 * ntp + (lane >> 4)) * 8) * 2);
                        ldm_x4_t(v0, v1, v2, v3, addr);
                        mma_f16(o[2 * ntp][0], o[2 * ntp][1], o[2 * ntp][2], o[2 * ntp][3],
                                a0, a1, a2, a3, v0, v1);
                        mma_f16(o[2 * ntp + 1][0], o[2 * ntp + 1][1],
                                o[2 * ntp + 1][2], o[2 * ntp + 1][3],
                                a0, a1, a2, a3, v2, v3);
                    }
                }
            }
            __syncthreads();
        }

        // ---- write this tile's O ----
        float inv0 = 1.f / l0, inv1 = 1.f / l1;
        int b = bh >> 4, h = bh & 15;
        __half* y0 = g_yh + ((size_t)b * Tc + r0) * Cc + h * HDc;
        __half* y1 = y0 + (size_t)8 * Cc;
#pragma unroll
        for (int nt = 0; nt < 8; nt++) {
            *(__half2*)&y0[nt * 8 + 2 * c] =
                __float22half2_rn(make_float2(o[nt][0] * inv0, o[nt][1] * inv0));
            *(__half2*)&y1[nt * 8 + 2 * c] =
                __float22half2_rn(make_float2(o[nt][2] * inv1, o[nt][3] * inv1));
        }
    }
}

// ---------------------------------------------------------------------------
// Launch
// ---------------------------------------------------------------------------
extern "C" void kernel_launch(void* const* d_in, const int* in_sizes, int n_in,
                              void* d_out, int out_size)
{
    const float* x      = (const float*)d_in[0];
    const float* W_attn = (const float*)d_in[1];
    const float* b_attn = (const float*)d_in[2];
    const float* W_proj = (const float*)d_in[3];
    const float* b_proj = (const float*)d_in[4];
    float* out = (float*)d_out;

    __half *xh, *yh, *wa_t, *wp_t;
    cudaGetSymbolAddress((void**)&xh,   g_xh);
    cudaGetSymbolAddress((void**)&yh,   g_yh);
    cudaGetSymbolAddress((void**)&wa_t, g_wa_th);
    cudaGetSymbolAddress((void**)&wp_t, g_wp_th);

    static bool attr_done = false;
    if (!attr_done) {
        cudaFuncSetAttribute(gemm_h<1>, cudaFuncAttributeMaxDynamicSharedMemorySize, GEMM_SMEM);
        cudaFuncSetAttribute(gemm_h<0>, cudaFuncAttributeMaxDynamicSharedMemorySize, GEMM_SMEM);
        cudaFuncSetAttribute(attn_h, cudaFuncAttributeMaxDynamicSharedMemorySize, ATTN_SMEM);
        attr_done = true;
    }

    // Prep: x -> fp16; transpose+convert weights
    {
        int n4 = Bc * Tc * Cc / 4;
        conv_x_kernel<<<(n4 + 255) / 256, 256>>>(x, n4);
        transpose_conv<<<dim3(3 * Cc / 32, Cc / 32), dim3(32, 8)>>>(W_attn, wa_t, Cc, 3 * Cc);
        transpose_conv<<<dim3(Cc / 32, Cc / 32), dim3(32, 8)>>>(W_proj, wp_t, Cc, Cc);
    }
    // 1) QKV GEMM -> g_qh/g_kh/g_vh
    {
        dim3 grid(3 * Cc / BNg, Bc * Tc / BMg);
        gemm_h<1><<<grid, 256, GEMM_SMEM>>>(xh, wa_t, b_attn, nullptr, Cc, 3 * Cc);
    }
    // 2) FA2 attention (paired q-tiles, uniform 17 stages/block) -> g_yh
    {
        dim3 grid(NQT / 2, Bc * NHc);
        attn_h<<<grid, 256, ATTN_SMEM>>>();
    }
    // 3) projection GEMM -> out
    {
        dim3 grid(Cc / BNg, Bc * Tc / BMg);
        gemm_h<0><<<grid, 256, GEMM_SMEM>>>(yh, wp_t, b_proj, out, Cc, Cc);
    }
}

// round 17
// speedup vs baseline: 2.4183x; 1.0922x over previous
#include <cuda_runtime.h>
#include <cuda_fp16.h>
#include <cstdint>

// Problem constants
#define Bc  4
#define Tc  2048
#define Cc  1024
#define NHc 16
#define HDc 64

// ---------------------------------------------------------------------------
// Scratch (no cudaMalloc allowed)
// ---------------------------------------------------------------------------
__device__ __half g_qh[Bc * NHc * Tc * HDc];   // [B*NH, T, HD]
__device__ __half g_kh[Bc * NHc * Tc * HDc];
__device__ __half g_vh[Bc * NHc * Tc * HDc];
__device__ __half g_yh[Bc * Tc * Cc];          // attention out [B,T,C]
__device__ __half g_xh[Bc * Tc * Cc];          // fp16 x
__device__ __half g_wah[Cc * 3 * Cc];          // W_attn fp16 [K, N] (native layout)
__device__ __half g_wph[Cc * Cc];              // W_proj fp16 [K, N]

__device__ __forceinline__ uint32_t smem_u32(const void* p) {
    uint32_t a;
    asm("{ .reg .u64 t; cvta.to.shared.u64 t, %1; cvt.u32.u64 %0, t; }" : "=r"(a) : "l"(p));
    return a;
}
__device__ __forceinline__ void cp16(uint32_t dst, const void* src) {
    asm volatile("cp.async.cg.shared.global [%0], [%1], 16;" :: "r"(dst), "l"(src));
}
__device__ __forceinline__ void cp_commit() {
    asm volatile("cp.async.commit_group;" ::: "memory");
}
template <int N>
__device__ __forceinline__ void cp_wait() {
    asm volatile("cp.async.wait_group %0;" :: "n"(N) : "memory");
}
__device__ __forceinline__ uint32_t h2u(__half2 h) { return *reinterpret_cast<uint32_t*>(&h); }
__device__ __forceinline__ uint32_t packh(float a, float b) {
    return h2u(__float22half2_rn(make_float2(a, b)));
}

__device__ __forceinline__ void mma_f16(float& d0, float& d1, float& d2, float& d3,
                                        uint32_t a0, uint32_t a1, uint32_t a2, uint32_t a3,
                                        uint32_t b0, uint32_t b1)
{
    asm volatile(
        "mma.sync.aligned.m16n8k16.row.col.f32.f16.f16.f32 "
        "{%0,%1,%2,%3}, {%4,%5,%6,%7}, {%8,%9}, {%0,%1,%2,%3};"
        : "+f"(d0), "+f"(d1), "+f"(d2), "+f"(d3)
        : "r"(a0), "r"(a1), "r"(a2), "r"(a3), "r"(b0), "r"(b1));
}
__device__ __forceinline__ void ldm_x4(uint32_t& r0, uint32_t& r1, uint32_t& r2, uint32_t& r3,
                                       uint32_t addr)
{
    asm volatile("ldmatrix.sync.aligned.m8n8.x4.shared.b16 {%0,%1,%2,%3}, [%4];"
                 : "=r"(r0), "=r"(r1), "=r"(r2), "=r"(r3) : "r"(addr));
}
__device__ __forceinline__ void ldm_x4_t(uint32_t& r0, uint32_t& r1, uint32_t& r2, uint32_t& r3,
                                         uint32_t addr)
{
    asm volatile("ldmatrix.sync.aligned.m8n8.x4.trans.shared.b16 {%0,%1,%2,%3}, [%4];"
                 : "=r"(r0), "=r"(r1), "=r"(r2), "=r"(r3) : "r"(addr));
}

// ---------------------------------------------------------------------------
// fp16 mma GEMM: Out[M,N] = A[M,K] @ W[K,N] + bias.  W in NATIVE [K,N] layout;
// B fragments via ldmatrix.trans (pattern proven in attention's P@V path).
// BM=BN=128, BK=64, 256 threads, 64x32 warp tiles, cp.async 3-stage.
// A rows: GST=72-half stride; B k-rows: GSTB=136-half stride (both odd-granule).
// SCATTER=1: half epilogue into g_qh/g_kh/g_vh; else fp32 Out.
// ---------------------------------------------------------------------------
constexpr int BMg = 128, BNg = 128, BKg = 64;
constexpr int GST  = 72;                                // A: halves per smem row
constexpr int GSTB = 136;                               // B: halves per k-row
constexpr int A_HALVES = BMg * GST;                     // 9216
constexpr int B_HALVES = BKg * GSTB;                    // 8704
constexpr int STAGE_HALVES = A_HALVES + B_HALVES;       // 17920
constexpr int GEMM_SMEM = 3 * STAGE_HALVES * 2;         // 107520 B

template <int SCATTER>
__global__ __launch_bounds__(256, 2)
void gemm_h(const __half* __restrict__ A, const __half* __restrict__ W,
            const float* __restrict__ bias, float* __restrict__ Out,
            int K, int N)
{
    extern __shared__ __half sg[];

    const int tid  = threadIdx.x;
    const int lane = tid & 31;
    const int wid  = tid >> 5;
    const int g    = lane >> 2;
    const int c    = lane & 3;
    const int warp_m = (wid & 1) * 64;
    const int warp_n = (wid >> 1) * 32;
    const int lrow = lane & 15;
    const int lcol = (lane >> 4) * 8;

    const __half* Asrc0 = A + (size_t)blockIdx.y * BMg * K;
    const int n0blk = blockIdx.x * BNg;

    auto load_stage = [&](int kt, int st) {
        __half* sA = sg + st * STAGE_HALVES;
        __half* sB = sA + A_HALVES;
        const __half* Asrc = Asrc0 + kt * BKg;
        const __half* Wsrc = W + (size_t)(kt * BKg) * N + n0blk;
        // A: 128 rows x 64 halves = 1024 cp16
#pragma unroll
        for (int i = 0; i < 4; i++) {
            int ch = tid + i * 256;
            int row = ch >> 3, q = (ch & 7) * 8;
            cp16(smem_u32(sA + row * GST + q), Asrc + (size_t)row * K + q);
        }
        // B: 64 k-rows x 128 halves = 1024 cp16 (native [K,N] rows)
#pragma unroll
        for (int i = 0; i < 4; i++) {
            int ch = tid + i * 256;
            int row = ch >> 4, q = (ch & 15) * 8;
            cp16(smem_u32(sB + row * GSTB + q), Wsrc + (size_t)row * N + q);
        }
    };

    float acc[4][4][4];
#pragma unroll
    for (int i = 0; i < 4; i++)
#pragma unroll
        for (int j = 0; j < 4; j++)
#pragma unroll
            for (int r = 0; r < 4; r++) acc[i][j][r] = 0.f;

    const int NT = K / BKg;
    load_stage(0, 0); cp_commit();
    load_stage(1, 1); cp_commit();

    int st = 0;
    for (int kt = 0; kt < NT; kt++) {
        if (kt + 1 < NT) cp_wait<1>(); else cp_wait<0>();
        __syncthreads();

        const uint32_t sAu = smem_u32(sg + st * STAGE_HALVES);
        const uint32_t sBu = sAu + A_HALVES * 2;

#pragma unroll
        for (int ks = 0; ks < 4; ks++) {
            uint32_t af[4][4], bf[4][2];
#pragma unroll
            for (int mt = 0; mt < 4; mt++) {
                uint32_t addr = sAu + (uint32_t)(((warp_m + mt * 16 + lrow) * GST
                                                 + ks * 16 + lcol) * 2);
                ldm_x4(af[mt][0], af[mt][1], af[mt][2], af[mt][3], addr);
            }
            // B fragments via ldmatrix.trans on native [K,N] rows:
            // lanes 0-7: k+0..7 / n; 8-15: k+8..15 / n; 16-23: k+0..7 / n+8; 24-31: k+8..15 / n+8
#pragma unroll
            for (int bp = 0; bp < 2; bp++) {
                uint32_t addr = sBu + (uint32_t)(((ks * 16 + ((lane >> 3) & 1) * 8 + (lane & 7)) * GSTB
                                                 + warp_n + bp * 16 + (lane >> 4) * 8) * 2);
                ldm_x4_t(bf[2 * bp][0], bf[2 * bp][1],
                         bf[2 * bp + 1][0], bf[2 * bp + 1][1], addr);
            }
#pragma unroll
            for (int mt = 0; mt < 4; mt++)
#pragma unroll
                for (int nt = 0; nt < 4; nt++)
                    mma_f16(acc[mt][nt][0], acc[mt][nt][1], acc[mt][nt][2], acc[mt][nt][3],
                            af[mt][0], af[mt][1], af[mt][2], af[mt][3],
                            bf[nt][0], bf[nt][1]);
        }

        if (kt + 2 < NT) {
            int s2 = st + 2; if (s2 >= 3) s2 -= 3;
            load_stage(kt + 2, s2);
            cp_commit();
        }
        if (++st == 3) st = 0;
    }

#pragma unroll
    for (int mt = 0; mt < 4; mt++) {
#pragma unroll
        for (int nt = 0; nt < 4; nt++) {
            int n0 = n0blk + warp_n + nt * 8 + 2 * c;
            float2 bb = *(const float2*)(bias + n0);
            int m0 = blockIdx.y * BMg + warp_m + mt * 16 + g;
#pragma unroll
            for (int rh = 0; rh < 2; rh++) {
                int m = m0 + rh * 8;
                float vx = acc[mt][nt][2 * rh + 0] + bb.x;
                float vy = acc[mt][nt][2 * rh + 1] + bb.y;
                if (SCATTER) {
                    __half2 hv = __float22half2_rn(make_float2(vx, vy));
                    int which = n0 >> 10, c0 = n0 & 1023;
                    int h = c0 >> 6, d = c0 & 63;
                    int b = m >> 11, t = m & 2047;
                    __half* dst = (which == 0) ? g_qh : ((which == 1) ? g_kh : g_vh);
                    *(__half2*)&dst[(((size_t)(b * NHc + h)) * Tc + t) * HDc + d] = hv;
                } else {
                    *(float2*)&Out[(size_t)m * N + n0] = make_float2(vx, vy);
                }
            }
        }
    }
}

// ---------------------------------------------------------------------------
// Single merged prep: fp32->fp16 for x, W_attn, W_proj (no transposes needed)
// ---------------------------------------------------------------------------
constexpr int XN4  = Bc * Tc * Cc / 4;        // 2097152
constexpr int WAN4 = 3 * Cc * Cc / 4;         // 786432
constexpr int WPN4 = Cc * Cc / 4;             // 262144

__global__ void conv_all(const float* __restrict__ x,
                         const float* __restrict__ wa,
                         const float* __restrict__ wp)
{
    int i = blockIdx.x * blockDim.x + threadIdx.x;
    const float* src;
    __half* dst;
    int base;
    if (i < XN4)              { src = x;  dst = g_xh;  base = i; }
    else if (i < XN4 + WAN4)  { src = wa; dst = g_wah; base = i - XN4; }
    else if (i < XN4 + WAN4 + WPN4) { src = wp; dst = g_wph; base = i - XN4 - WAN4; }
    else return;
    float4 v = ((const float4*)src)[base];
    ((__half2*)dst)[2 * base]     = __float22half2_rn(make_float2(v.x, v.y));
    ((__half2*)dst)[2 * base + 1] = __float22half2_rn(make_float2(v.z, v.w));
}

// ---------------------------------------------------------------------------
// FA2 attention (R15 — unchanged): paired q-tiles, 128-key stages, chunk skip.
// ---------------------------------------------------------------------------
constexpr int QTile = 128;
constexpr int NQT   = Tc / QTile;                        // 16
constexpr int KStage = 128;
constexpr int KVSH  = 72;
constexpr int ATTN_SMEM = 2 * 2 * KStage * KVSH * 2;     // 73728 B

__global__ __launch_bounds__(256, 2)
void attn_h()
{
    extern __shared__ __half smh[];
    __half* KsBase = smh;
    __half* VsBase = smh + 2 * KStage * KVSH;

    const int bh  = blockIdx.y;
    const int tid = threadIdx.x;
    const int lane = tid & 31;
    const int w   = tid >> 5;
    const int g   = lane >> 2;
    const int c   = lane & 3;

    const __half* gq = g_qh + (size_t)bh * Tc * HDc;
    const __half* gk = g_kh + (size_t)bh * Tc * HDc;
    const __half* gv = g_vh + (size_t)bh * Tc * HDc;

    const __half2 scl = __float2half2_rn(0.125f);

    auto load_kv = [&](int t, int buf) {
        const __half* ksrc = gk + (size_t)t * KStage * HDc;
        const __half* vsrc = gv + (size_t)t * KStage * HDc;
        __half* kd = KsBase + buf * KStage * KVSH;
        __half* vd = VsBase + buf * KStage * KVSH;
#pragma unroll
        for (int i = 0; i < 4; i++) {
            int id = tid + i * 256;
            int row = id >> 3, ch = (id & 7) * 8;
            cp16(smem_u32(kd + row * KVSH + ch), ksrc + row * HDc + ch);
            cp16(smem_u32(vd + row * KVSH + ch), vsrc + row * HDc + ch);
        }
    };

#pragma unroll 1
    for (int pass = 0; pass < 2; pass++) {
        const int qt = (pass == 0) ? (NQT - 1 - blockIdx.x) : blockIdx.x;
        const int qb = qt * QTile;
        const int r0 = qb + w * 16 + g;
        const int wlast = qb + w * 16 + 15;

        const __half2* q0p = (const __half2*)(gq + (size_t)r0 * HDc);
        const __half2* q1p = (const __half2*)(gq + (size_t)(r0 + 8) * HDc);
        uint32_t aq[4][4];
#pragma unroll
        for (int kk = 0; kk < 4; kk++) {
            aq[kk][0] = h2u(__hmul2(q0p[8 * kk + c],     scl));
            aq[kk][1] = h2u(__hmul2(q1p[8 * kk + c],     scl));
            aq[kk][2] = h2u(__hmul2(q0p[8 * kk + c + 4], scl));
            aq[kk][3] = h2u(__hmul2(q1p[8 * kk + c + 4], scl));
        }

        float o[8][4];
#pragma unroll
        for (int nt = 0; nt < 8; nt++)
#pragma unroll
            for (int j = 0; j < 4; j++) o[nt][j] = 0.f;
        float m0 = -1e30f, m1 = -1e30f, l0 = 0.f, l1 = 0.f;

        const int NT = qt + 1;
        load_kv(0, 0); cp_commit();

        for (int t = 0; t < NT; t++) {
            const int buf = t & 1;
            if (t + 1 < NT) { load_kv(t + 1, buf ^ 1); cp_commit(); cp_wait<1>(); }
            else            { cp_wait<0>(); }
            __syncthreads();

            const uint32_t ksb0 = smem_u32(KsBase + buf * KStage * KVSH);
            const uint32_t vsb0 = smem_u32(VsBase + buf * KStage * KVSH);

#pragma unroll
            for (int ch2 = 0; ch2 < 2; ch2++) {
                const int kb = t * KStage + ch2 * 64;
                if (kb > wlast) continue;
                const uint32_t ksb = ksb0 + (uint32_t)(ch2 * 64 * KVSH * 2);
                const uint32_t vsb = vsb0 + (uint32_t)(ch2 * 64 * KVSH * 2);

                float s[8][4];
#pragma unroll
                for (int nt = 0; nt < 8; nt++)
#pragma unroll
                    for (int j = 0; j < 4; j++) s[nt][j] = 0.f;

#pragma unroll
                for (int nt = 0; nt < 8; nt++) {
                    uint32_t k0r, k1r, k2r, k3r;
                    uint32_t addr = ksb + (uint32_t)(((nt * 8 + (lane & 7)) * KVSH
                                                     + (lane >> 3) * 8) * 2);
                    ldm_x4(k0r, k1r, k2r, k3r, addr);
                    mma_f16(s[nt][0], s[nt][1], s[nt][2], s[nt][3],
                            aq[0][0], aq[0][1], aq[0][2], aq[0][3], k0r, k1r);
                    mma_f16(s[nt][0], s[nt][1], s[nt][2], s[nt][3],
                            aq[1][0], aq[1][1], aq[1][2], aq[1][3], k2r, k3r);
                    ldm_x4(k0r, k1r, k2r, k3r, addr + 64);
                    mma_f16(s[nt][0], s[nt][1], s[nt][2], s[nt][3],
                            aq[2][0], aq[2][1], aq[2][2], aq[2][3], k0r, k1r);
                    mma_f16(s[nt][0], s[nt][1], s[nt][2], s[nt][3],
                            aq[3][0], aq[3][1], aq[3][2], aq[3][3], k2r, k3r);
                }

                if (kb + 63 > qb + w * 16) {
#pragma unroll
                    for (int nt = 0; nt < 8; nt++) {
                        int key0 = kb + nt * 8 + 2 * c;
                        if (key0     > r0)     s[nt][0] = -1e30f;
                        if (key0 + 1 > r0)     s[nt][1] = -1e30f;
                        if (key0     > r0 + 8) s[nt][2] = -1e30f;
                        if (key0 + 1 > r0 + 8) s[nt][3] = -1e30f;
                    }
                }

                float rm0 = -1e30f, rm1 = -1e30f;
#pragma unroll
                for (int nt = 0; nt < 8; nt++) {
                    rm0 = fmaxf(rm0, fmaxf(s[nt][0], s[nt][1]));
                    rm1 = fmaxf(rm1, fmaxf(s[nt][2], s[nt][3]));
                }
                rm0 = fmaxf(rm0, __shfl_xor_sync(0xffffffffu, rm0, 1));
                rm0 = fmaxf(rm0, __shfl_xor_sync(0xffffffffu, rm0, 2));
                rm1 = fmaxf(rm1, __shfl_xor_sync(0xffffffffu, rm1, 1));
                rm1 = fmaxf(rm1, __shfl_xor_sync(0xffffffffu, rm1, 2));

                float mn0 = fmaxf(m0, rm0), mn1 = fmaxf(m1, rm1);
                float corr0 = __expf(m0 - mn0), corr1 = __expf(m1 - mn1);
                m0 = mn0; m1 = mn1;

                float ls0 = 0.f, ls1 = 0.f;
                uint32_t pu0[8], pu1[8];
#pragma unroll
                for (int nt = 0; nt < 8; nt++) {
                    float p0 = __expf(s[nt][0] - m0);
                    float p1 = __expf(s[nt][1] - m0);
                    float p2 = __expf(s[nt][2] - m1);
                    float p3 = __expf(s[nt][3] - m1);
                    ls0 += p0 + p1;  ls1 += p2 + p3;
                    pu0[nt] = packh(p0, p1);
                    pu1[nt] = packh(p2, p3);
                }
                ls0 += __shfl_xor_sync(0xffffffffu, ls0, 1);
                ls0 += __shfl_xor_sync(0xffffffffu, ls0, 2);
                ls1 += __shfl_xor_sync(0xffffffffu, ls1, 1);
                ls1 += __shfl_xor_sync(0xffffffffu, ls1, 2);
                l0 = l0 * corr0 + ls0;
                l1 = l1 * corr1 + ls1;
#pragma unroll
                for (int nt = 0; nt < 8; nt++) {
                    o[nt][0] *= corr0; o[nt][1] *= corr0;
                    o[nt][2] *= corr1; o[nt][3] *= corr1;
                }

#pragma unroll
                for (int kk2 = 0; kk2 < 4; kk2++) {
                    uint32_t a0 = pu0[2 * kk2],     a1 = pu1[2 * kk2];
                    uint32_t a2 = pu0[2 * kk2 + 1], a3 = pu1[2 * kk2 + 1];
#pragma unroll
                    for (int ntp = 0; ntp < 4; ntp++) {
                        uint32_t v0, v1, v2, v3;
                        uint32_t addr = vsb + (uint32_t)((
                            (kk2 * 16 + ((lane >> 3) & 1) * 8 + (lane & 7)) * KVSH +
                            (2 * ntp + (lane >> 4)) * 8) * 2);
                        ldm_x4_t(v0, v1, v2, v3, addr);
                        mma_f16(o[2 * ntp][0], o[2 * ntp][1], o[2 * ntp][2], o[2 * ntp][3],
                                a0, a1, a2, a3, v0, v1);
                        mma_f16(o[2 * ntp + 1][0], o[2 * ntp + 1][1],
                                o[2 * ntp + 1][2], o[2 * ntp + 1][3],
                                a0, a1, a2, a3, v2, v3);
                    }
                }
            }
            __syncthreads();
        }

        float inv0 = 1.f / l0, inv1 = 1.f / l1;
        int b = bh >> 4, h = bh & 15;
        __half* y0 = g_yh + ((size_t)b * Tc + r0) * Cc + h * HDc;
        __half* y1 = y0 + (size_t)8 * Cc;
#pragma unroll
        for (int nt = 0; nt < 8; nt++) {
            *(__half2*)&y0[nt * 8 + 2 * c] =
                __float22half2_rn(make_float2(o[nt][0] * inv0, o[nt][1] * inv0));
            *(__half2*)&y1[nt * 8 + 2 * c] =
                __float22half2_rn(make_float2(o[nt][2] * inv1, o[nt][3] * inv1));
        }
    }
}

// ---------------------------------------------------------------------------
// Launch
// ---------------------------------------------------------------------------
extern "C" void kernel_launch(void* const* d_in, const int* in_sizes, int n_in,
                              void* d_out, int out_size)
{
    const float* x      = (const float*)d_in[0];
    const float* W_attn = (const float*)d_in[1];
    const float* b_attn = (const float*)d_in[2];
    const float* W_proj = (const float*)d_in[3];
    const float* b_proj = (const float*)d_in[4];
    float* out = (float*)d_out;

    __half *xh, *yh, *wah, *wph;
    cudaGetSymbolAddress((void**)&xh,  g_xh);
    cudaGetSymbolAddress((void**)&yh,  g_yh);
    cudaGetSymbolAddress((void**)&wah, g_wah);
    cudaGetSymbolAddress((void**)&wph, g_wph);

    static bool attr_done = false;
    if (!attr_done) {
        cudaFuncSetAttribute(gemm_h<1>, cudaFuncAttributeMaxDynamicSharedMemorySize, GEMM_SMEM);
        cudaFuncSetAttribute(gemm_h<0>, cudaFuncAttributeMaxDynamicSharedMemorySize, GEMM_SMEM);
        cudaFuncSetAttribute(attn_h, cudaFuncAttributeMaxDynamicSharedMemorySize, ATTN_SMEM);
        attr_done = true;
    }

    // Prep: ONE kernel converts x + both weights to fp16 (native layouts)
    {
        int total = XN4 + WAN4 + WPN4;
        conv_all<<<(total + 255) / 256, 256>>>(x, W_attn, W_proj);
    }
    // 1) QKV GEMM -> g_qh/g_kh/g_vh
    {
        dim3 grid(3 * Cc / BNg, Bc * Tc / BMg);
        gemm_h<1><<<grid, 256, GEMM_SMEM>>>(xh, wah, b_attn, nullptr, Cc, 3 * Cc);
    }
    // 2) FA2 attention (paired q-tiles) -> g_yh
    {
        dim3 grid(NQT / 2, Bc * NHc);
        attn_h<<<grid, 256, ATTN_SMEM>>>();
    }
    // 3) projection GEMM -> out
    {
        dim3 grid(Cc / BNg, Bc * Tc / BMg);
        gemm_h<0><<<grid, 256, GEMM_SMEM>>>(yh, wph, b_proj, out, Cc, Cc);
    }
}